// round 14
// baseline (speedup 1.0000x reference)
#include <cuda_runtime.h>
#include <cuda_bf16.h>
#include <cuda_fp16.h>
#include <math.h>
#include <stdint.h>

// Problem constants
#define BATCH 4
#define SEQ   1024
#define DM    512
#define NH    8
#define DH    64
#define ROWS  (BATCH*SEQ)          // 4096

// ---------------------------------------------------------------------------
// Scratch (__device__ globals: allocation-free rule)
// ---------------------------------------------------------------------------
__device__ __nv_bfloat16 g_xh[ROWS*DM];     // x split hi
__device__ __nv_bfloat16 g_xl[ROWS*DM];     // x split lo
__device__ __nv_bfloat16 g_Ah[ROWS*DM];     // attention out split hi [b][n][h][d]
__device__ __nv_bfloat16 g_Al[ROWS*DM];     // attention out split lo
// Transposed weights (n-major rows), bf16 split:
// rows 0..1535 = WQ|WK|WV, rows 1536..2047 = WO
__device__ __nv_bfloat16 g_Wth[2048*512];
__device__ __nv_bfloat16 g_Wtl[2048*512];
// Attention-layout splits: [b][h][n][d]
#define BHND (32*1024*64)
__device__ __nv_bfloat16 g_Qbh[BHND], g_Qbl[BHND];   // Q bf16 hi/lo
__device__ __nv_bfloat16 g_Kbh[BHND], g_Kbl[BHND];   // K bf16 hi/lo
__device__ __half        g_Vfh[BHND], g_Vfl[BHND];   // V fp16 hi/lo
// RoPE cos/sin table: [h][n][m] -> float2 (cos, sin)
__device__ float2 g_cs[NH*SEQ*32];

// ---------------------------------------------------------------------------
// Helpers
// ---------------------------------------------------------------------------
__device__ __forceinline__ uint32_t smem_u32(const void* p) {
    uint32_t a;
    asm("{ .reg .u64 t; cvta.to.shared.u64 t, %1; cvt.u32.u64 %0, t; }" : "=r"(a) : "l"(p));
    return a;
}
__device__ __forceinline__ void ldsm_x4(uint32_t addr, uint32_t& r0, uint32_t& r1,
                                        uint32_t& r2, uint32_t& r3) {
    asm volatile("ldmatrix.sync.aligned.m8n8.x4.shared.b16 {%0,%1,%2,%3}, [%4];"
                 : "=r"(r0), "=r"(r1), "=r"(r2), "=r"(r3) : "r"(addr));
}
__device__ __forceinline__ void ldsm_x4t(uint32_t addr, uint32_t& r0, uint32_t& r1,
                                         uint32_t& r2, uint32_t& r3) {
    asm volatile("ldmatrix.sync.aligned.m8n8.x4.trans.shared.b16 {%0,%1,%2,%3}, [%4];"
                 : "=r"(r0), "=r"(r1), "=r"(r2), "=r"(r3) : "r"(addr));
}
__device__ __forceinline__ void mma_bf16(float* c, const uint32_t* a,
                                         uint32_t b0, uint32_t b1) {
    asm volatile(
        "mma.sync.aligned.m16n8k16.row.col.f32.bf16.bf16.f32 "
        "{%0,%1,%2,%3}, {%4,%5,%6,%7}, {%8,%9}, {%0,%1,%2,%3};"
        : "+f"(c[0]), "+f"(c[1]), "+f"(c[2]), "+f"(c[3])
        : "r"(a[0]), "r"(a[1]), "r"(a[2]), "r"(a[3]), "r"(b0), "r"(b1));
}
__device__ __forceinline__ void mma_fp16(float* c, const uint32_t* a,
                                         uint32_t b0, uint32_t b1) {
    asm volatile(
        "mma.sync.aligned.m16n8k16.row.col.f32.f16.f16.f32 "
        "{%0,%1,%2,%3}, {%4,%5,%6,%7}, {%8,%9}, {%0,%1,%2,%3};"
        : "+f"(c[0]), "+f"(c[1]), "+f"(c[2]), "+f"(c[3])
        : "r"(a[0]), "r"(a[1]), "r"(a[2]), "r"(a[3]), "r"(b0), "r"(b1));
}
__device__ __forceinline__ float ex2f(float x) {
    float y;
    asm("ex2.approx.f32 %0, %1;" : "=f"(y) : "f"(x));
    return y;
}
__device__ __forceinline__ uint32_t b2u(__nv_bfloat162 v) {
    return *reinterpret_cast<uint32_t*>(&v);
}
__device__ __forceinline__ uint32_t h2u(__half2 v) {
    return *reinterpret_cast<uint32_t*>(&v);
}
__device__ __forceinline__ void cp16(uint32_t dst, const void* src) {
    asm volatile("cp.async.cg.shared.global [%0], [%1], 16;" :: "r"(dst), "l"(src));
}
#define CP_COMMIT() asm volatile("cp.async.commit_group;" ::: "memory")
#define CP_WAIT0()  asm volatile("cp.async.wait_group 0;" ::: "memory")

// ---------------------------------------------------------------------------
// Fused prep kernel
// ---------------------------------------------------------------------------
__global__ void prep_kernel(const float* __restrict__ x,
                            const float* __restrict__ pos,
                            const float* __restrict__ freqs,
                            const float* __restrict__ WQ,
                            const float* __restrict__ WK,
                            const float* __restrict__ WV,
                            const float* __restrict__ WO) {
    const int bid = blockIdx.x;
    if (bid < 2048) {
        int i = bid * 256 + threadIdx.x;
        float4 v = ((const float4*)x)[i];
        float vv[4] = {v.x, v.y, v.z, v.w};
#pragma unroll
        for (int j = 0; j < 4; j++) {
            __nv_bfloat16 h = __float2bfloat16(vv[j]);
            __nv_bfloat16 l = __float2bfloat16(vv[j] - __bfloat162float(h));
            g_xh[4 * i + j] = h;
            g_xl[4 * i + j] = l;
        }
        if (i < NH * SEQ * 32) {
            int m = i & 31;
            int n = (i >> 5) & 1023;
            int h = i >> 15;
            float ang = pos[n * 2 + 0] * freqs[(h * 32 + m) * 2 + 0]
                      + pos[n * 2 + 1] * freqs[(h * 32 + m) * 2 + 1];
            float s, c;
            sincosf(ang, &s, &c);
            g_cs[i] = make_float2(c, s);
        }
    } else {
        __shared__ float t[32][33];
        const int wb = bid - 2048;          // 0..1023
        const int z  = wb >> 8;             // 0..3
        const float* W = (z == 0) ? WQ : (z == 1) ? WK : (z == 2) ? WV : WO;
        const int zoff = z * 512;
        const int rest = wb & 255;
        const int k0 = (rest & 15) * 32, n0 = (rest >> 4) * 32;
        const int tx = threadIdx.x & 31, ty = threadIdx.x >> 5;   // 32 x 8
#pragma unroll
        for (int i = 0; i < 4; i++)
            t[ty + i * 8][tx] = W[(k0 + ty + i * 8) * 512 + n0 + tx];
        __syncthreads();
#pragma unroll
        for (int i = 0; i < 4; i++) {
            float v = t[tx][ty + i * 8];
            __nv_bfloat16 h = __float2bfloat16(v);
            __nv_bfloat16 l = __float2bfloat16(v - __bfloat162float(h));
            int dst = (zoff + n0 + ty + i * 8) * 512 + k0 + tx;
            g_Wth[dst] = h;
            g_Wtl[dst] = l;
        }
    }
}

// ---------------------------------------------------------------------------
// Split-bf16 GEMM core: block tile 64x128, BK=32, 4 warps (1m x 4n),
// warp tile 64x32 (identical per-warp geometry to before).
// cp.async double-buffered, one barrier per chunk. 128-thread blocks.
// Stage layout: [Ah(64) | Al(64) | Bh(128) | Bl(128)], rows padded APAD.
// ---------------------------------------------------------------------------
#define APAD 40
#define A_BY (64*APAD*2)     // 5120 B per A array
#define B_BY (128*APAD*2)    // 10240 B per B array
#define GSTAGE (2*A_BY + 2*B_BY)  // 30720 B per stage
#define GEMM_SMEM (2*GSTAGE)      // 61440 B

struct GemmFrag { float acc[4][4][4]; };

__device__ __forceinline__ void gemm_core(
    const __nv_bfloat16* __restrict__ Ah, const __nv_bfloat16* __restrict__ Al,
    const __nv_bfloat16* __restrict__ Bh, const __nv_bfloat16* __restrict__ Bl,
    GemmFrag& fr)
{
    extern __shared__ char sm[];
    const uint32_t sb = smem_u32(sm);
    const int tid  = threadIdx.x;
    const int wid  = tid >> 5, lane = tid & 31;   // wid = wn (0..3)
    const int g    = lane >> 3, r = lane & 7;

#pragma unroll
    for (int i = 0; i < 4; i++)
#pragma unroll
        for (int j = 0; j < 4; j++)
#pragma unroll
            for (int k = 0; k < 4; k++) fr.acc[i][j][k] = 0.f;

    // A fill: 256 chunks per array, 2 per thread; B: 512 chunks, 4 per thread
    const int ca0 = tid, ca1 = tid + 128;
    const uint32_t dA0 = sb + (ca0 >> 2) * (APAD * 2) + (ca0 & 3) * 16;
    const uint32_t dA1 = sb + (ca1 >> 2) * (APAD * 2) + (ca1 & 3) * 16;
    const size_t sA0 = (size_t)(ca0 >> 2) * 512 + (ca0 & 3) * 8;
    const size_t sA1 = (size_t)(ca1 >> 2) * 512 + (ca1 & 3) * 8;
    uint32_t dB[4];
    size_t sB[4];
#pragma unroll
    for (int u = 0; u < 4; u++) {
        int c = tid + u * 128;
        dB[u] = sb + 2 * A_BY + (c >> 2) * (APAD * 2) + (c & 3) * 16;
        sB[u] = (size_t)(c >> 2) * 512 + (c & 3) * 8;
    }

    const uint32_t aBH = sb + ((g & 1) * 8 + r) * (APAD * 2) + ((g >> 1) * 8) * 2;
    const uint32_t aBL = aBH + A_BY;
    const uint32_t bBH = sb + 2 * A_BY + (wid * 32 + (g >> 1) * 8 + r) * (APAD * 2) + ((g & 1) * 8) * 2;
    const uint32_t bBL = bBH + B_BY;

    // prologue: stage chunk 0 into buffer 0
    {
        cp16(dA0, Ah + sA0); cp16(dA1, Ah + sA1);
        cp16(dA0 + A_BY, Al + sA0); cp16(dA1 + A_BY, Al + sA1);
#pragma unroll
        for (int u = 0; u < 4; u++) {
            cp16(dB[u], Bh + sB[u]);
            cp16(dB[u] + B_BY, Bl + sB[u]);
        }
        CP_COMMIT();
    }

#pragma unroll 1
    for (int kc = 0; kc < 16; kc++) {
        CP_WAIT0();
        __syncthreads();
        if (kc < 15) {
            const int k1 = (kc + 1) * 32;
            const uint32_t off = ((kc + 1) & 1) * GSTAGE;
            cp16(dA0 + off, Ah + sA0 + k1); cp16(dA1 + off, Ah + sA1 + k1);
            cp16(dA0 + off + A_BY, Al + sA0 + k1); cp16(dA1 + off + A_BY, Al + sA1 + k1);
#pragma unroll
            for (int u = 0; u < 4; u++) {
                cp16(dB[u] + off, Bh + sB[u] + k1);
                cp16(dB[u] + off + B_BY, Bl + sB[u] + k1);
            }
            CP_COMMIT();
        }

        const uint32_t off = (kc & 1) * GSTAGE;
#pragma unroll
        for (int ks = 0; ks < 2; ks++) {
            const uint32_t koff = off + ks * 32;
            uint32_t ah[4][4], al[4][4], bh[2][4], bl[2][4];
#pragma unroll
            for (int mt = 0; mt < 4; mt++) {
                ldsm_x4(aBH + mt * (16 * APAD * 2) + koff, ah[mt][0], ah[mt][1], ah[mt][2], ah[mt][3]);
                ldsm_x4(aBL + mt * (16 * APAD * 2) + koff, al[mt][0], al[mt][1], al[mt][2], al[mt][3]);
            }
#pragma unroll
            for (int nt = 0; nt < 2; nt++) {
                ldsm_x4(bBH + nt * (16 * APAD * 2) + koff, bh[nt][0], bh[nt][1], bh[nt][2], bh[nt][3]);
                ldsm_x4(bBL + nt * (16 * APAD * 2) + koff, bl[nt][0], bl[nt][1], bl[nt][2], bl[nt][3]);
            }
#pragma unroll
            for (int mt = 0; mt < 4; mt++)
#pragma unroll
                for (int ng = 0; ng < 4; ng++) {
                    const int nt = ng >> 1, p = (ng & 1) * 2;
                    mma_bf16(fr.acc[mt][ng], ah[mt], bh[nt][p], bh[nt][p + 1]);
                    mma_bf16(fr.acc[mt][ng], ah[mt], bl[nt][p], bl[nt][p + 1]);
                    mma_bf16(fr.acc[mt][ng], al[mt], bh[nt][p], bh[nt][p + 1]);
                }
        }
    }
}

// QKV projection: grid (12, 64), 128 threads. Fused RoPE + split epilogue.
__global__ void __launch_bounds__(128) qkv_gemm_mma() {
    const int gn0 = blockIdx.x * 128;
    const int sel = gn0 >> 9;
    const int hb  = (gn0 >> 6) & 7;
    const int m0  = blockIdx.y * 64;

    GemmFrag fr;
    gemm_core(g_xh + (size_t)m0 * 512, g_xl + (size_t)m0 * 512,
              g_Wth + (size_t)gn0 * 512, g_Wtl + (size_t)gn0 * 512, fr);

    const int wid = threadIdx.x >> 5, lane = threadIdx.x & 31;

#pragma unroll
    for (int mt = 0; mt < 4; mt++) {
        int row0 = mt * 16 + (lane >> 2);
#pragma unroll
        for (int ng = 0; ng < 4; ng++) {
            int col = wid * 32 + ng * 8 + (lane & 3) * 2;
            int h2 = hb + (col >> 6);
            int hd = col & 63;
            float v0 = fr.acc[mt][ng][0], v1 = fr.acc[mt][ng][1];
            float v2 = fr.acc[mt][ng][2], v3 = fr.acc[mt][ng][3];
            int tok0 = m0 + row0, tok1 = tok0 + 8;
            size_t off0 = ((size_t)((tok0 >> 10) * 8 + h2) * 1024 + (tok0 & 1023)) * 64 + hd;
            size_t off1 = ((size_t)((tok1 >> 10) * 8 + h2) * 1024 + (tok1 & 1023)) * 64 + hd;
            if (sel == 2) {
                __half2 hi0 = __floats2half2_rn(v0, v1);
                __half2 hi1 = __floats2half2_rn(v2, v3);
                float2 f0 = __half22float2(hi0);
                float2 f1 = __half22float2(hi1);
                __half2 lo0 = __floats2half2_rn(v0 - f0.x, v1 - f0.y);
                __half2 lo1 = __floats2half2_rn(v2 - f1.x, v3 - f1.y);
                *(uint32_t*)&g_Vfh[off0] = h2u(hi0);
                *(uint32_t*)&g_Vfl[off0] = h2u(lo0);
                *(uint32_t*)&g_Vfh[off1] = h2u(hi1);
                *(uint32_t*)&g_Vfl[off1] = h2u(lo1);
            } else {
                int mp = hd >> 1;
                float2 cs0 = g_cs[(h2 * 1024 + (tok0 & 1023)) * 32 + mp];
                float2 cs1 = g_cs[(h2 * 1024 + (tok1 & 1023)) * 32 + mp];
                float a0 = v0, b0 = v1;
                v0 = a0 * cs0.x - b0 * cs0.y;
                v1 = a0 * cs0.y + b0 * cs0.x;
                float a1 = v2, b1 = v3;
                v2 = a1 * cs1.x - b1 * cs1.y;
                v3 = a1 * cs1.y + b1 * cs1.x;
                __nv_bfloat16* Dh = (sel == 0) ? g_Qbh : g_Kbh;
                __nv_bfloat16* Dl = (sel == 0) ? g_Qbl : g_Kbl;
                __nv_bfloat162 hi0 = __floats2bfloat162_rn(v0, v1);
                __nv_bfloat162 hi1 = __floats2bfloat162_rn(v2, v3);
                float2 f0 = __bfloat1622float2(hi0);
                float2 f1 = __bfloat1622float2(hi1);
                __nv_bfloat162 lo0 = __floats2bfloat162_rn(v0 - f0.x, v1 - f0.y);
                __nv_bfloat162 lo1 = __floats2bfloat162_rn(v2 - f1.x, v3 - f1.y);
                *(uint32_t*)&Dh[off0] = b2u(hi0);
                *(uint32_t*)&Dl[off0] = b2u(lo0);
                *(uint32_t*)&Dh[off1] = b2u(hi1);
                *(uint32_t*)&Dl[off1] = b2u(lo1);
            }
        }
    }
}

// Output projection: grid (4, 64), 128 threads, fp32 direct to out.
__global__ void __launch_bounds__(128) out_gemm_mma(float* __restrict__ out) {
    const int n0 = blockIdx.x * 128;
    const int m0 = blockIdx.y * 64;
    GemmFrag fr;
    gemm_core(g_Ah + (size_t)m0 * 512, g_Al + (size_t)m0 * 512,
              g_Wth + (size_t)(1536 + n0) * 512, g_Wtl + (size_t)(1536 + n0) * 512, fr);

    const int wid = threadIdx.x >> 5, lane = threadIdx.x & 31;
    float* C = out + (size_t)m0 * 512 + n0;
#pragma unroll
    for (int mt = 0; mt < 4; mt++) {
        int row0 = mt * 16 + (lane >> 2);
#pragma unroll
        for (int ng = 0; ng < 4; ng++) {
            int col = wid * 32 + ng * 8 + (lane & 3) * 2;
            *(float2*)(C + (size_t)row0 * 512 + col) =
                make_float2(fr.acc[mt][ng][0], fr.acc[mt][ng][1]);
            *(float2*)(C + (size_t)(row0 + 8) * 512 + col) =
                make_float2(fr.acc[mt][ng][2], fr.acc[mt][ng][3]);
        }
    }
}

// ---------------------------------------------------------------------------
// Tensor-core flash attention (unchanged from R13):
//   S = 3-term split-bf16; O = fp16 P x (Vfh + Vfl)
// ---------------------------------------------------------------------------
#define APAD2 72
#define KBY   (64*APAD2*2)     // 9216 B per array
#define KBUF  (4*KBY)          // 36864 B per stage
#define QOFF  (2*KBUF)         // 73728
#define QBY   (128*APAD2*2)    // 18432 B per Q array
#define ATTN_SMEM (QOFF + 2*QBY)   // 110592 B

__global__ void __launch_bounds__(128) attn_mma_kernel()
{
    extern __shared__ char sm[];
    const uint32_t sb = smem_u32(sm);

    const int bh = blockIdx.y;
    const int b = bh >> 3, h = bh & 7;
    const int q0 = blockIdx.x * 128;
    const int tid = threadIdx.x, wid = tid >> 5, lane = tid & 31;
    const int g = lane >> 3, r = lane & 7;
    const float cs = 0.25500300f;    // (1/sqrt(32)) * log2(e)

    const size_t base = (size_t)bh * SEQ * 64;
    const __nv_bfloat16* Qh = g_Qbh + base + (size_t)q0 * 64;
    const __nv_bfloat16* Ql = g_Qbl + base + (size_t)q0 * 64;
    const __nv_bfloat16* Kh = g_Kbh + base;
    const __nv_bfloat16* Kl = g_Kbl + base;
    const __half*        Vh = g_Vfh + base;
    const __half*        Vl = g_Vfl + base;

    uint32_t e[4];
    size_t t[4];
#pragma unroll
    for (int u = 0; u < 4; u++) {
        int idx = u * 128 + tid;
        e[u] = sb + (idx >> 3) * (APAD2 * 2) + (idx & 7) * 16;
        t[u] = (size_t)(idx >> 3) * 64 + (idx & 7) * 8;
    }

#pragma unroll
    for (int u = 0; u < 8; u++) {
        int idx = u * 128 + tid;
        uint32_t dst = sb + QOFF + (idx >> 3) * (APAD2 * 2) + (idx & 7) * 16;
        size_t src = (size_t)(idx >> 3) * 64 + (idx & 7) * 8;
        cp16(dst, Qh + src);
        cp16(dst + QBY, Ql + src);
    }
#pragma unroll
    for (int u = 0; u < 4; u++) {
        cp16(e[u] + 0 * KBY, Kh + t[u]);
        cp16(e[u] + 1 * KBY, Kl + t[u]);
        cp16(e[u] + 2 * KBY, Vh + t[u]);
        cp16(e[u] + 3 * KBY, Vl + t[u]);
    }
    CP_COMMIT();

    float accO[2][8][4];
#pragma unroll
    for (int mt = 0; mt < 2; mt++)
#pragma unroll
        for (int t2 = 0; t2 < 8; t2++)
#pragma unroll
            for (int j = 0; j < 4; j++) accO[mt][t2][j] = 0.f;
    float ll[2][2];
#pragma unroll
    for (int mt = 0; mt < 2; mt++) { ll[mt][0] = 0.f; ll[mt][1] = 0.f; }

#pragma unroll 1
    for (int kb = 0; kb < 16; kb++) {
        CP_WAIT0();
        __syncthreads();
        if (kb < 15) {
            const size_t koff = (size_t)(kb + 1) * 64 * 64;
            const uint32_t off = ((kb + 1) & 1) * KBUF;
#pragma unroll
            for (int u = 0; u < 4; u++) {
                cp16(e[u] + off + 0 * KBY, Kh + koff + t[u]);
                cp16(e[u] + off + 1 * KBY, Kl + koff + t[u]);
                cp16(e[u] + off + 2 * KBY, Vh + koff + t[u]);
                cp16(e[u] + off + 3 * KBY, Vl + koff + t[u]);
            }
            CP_COMMIT();
        }
        const uint32_t off = (kb & 1) * KBUF;

        // ---- S = Q K^T (split-bf16, 3 terms)
        float S[2][8][4];
#pragma unroll
        for (int mt = 0; mt < 2; mt++)
#pragma unroll
            for (int t2 = 0; t2 < 8; t2++)
#pragma unroll
                for (int j = 0; j < 4; j++) S[mt][t2][j] = 0.f;
#pragma unroll
        for (int ks = 0; ks < 4; ks++) {
            uint32_t qh[2][4], ql[2][4];
#pragma unroll
            for (int mt = 0; mt < 2; mt++) {
                uint32_t qa = sb + QOFF
                            + (wid * 32 + mt * 16 + (g & 1) * 8 + r) * (APAD2 * 2)
                            + (ks * 16 + (g >> 1) * 8) * 2;
                ldsm_x4(qa, qh[mt][0], qh[mt][1], qh[mt][2], qh[mt][3]);
                ldsm_x4(qa + QBY, ql[mt][0], ql[mt][1], ql[mt][2], ql[mt][3]);
            }
#pragma unroll
            for (int ng = 0; ng < 4; ng++) {
                uint32_t kh[4], kl[4];
                uint32_t aH = sb + off + (ng * 16 + (g >> 1) * 8 + r) * (APAD2 * 2)
                            + (ks * 16 + (g & 1) * 8) * 2;
                ldsm_x4(aH, kh[0], kh[1], kh[2], kh[3]);
                ldsm_x4(aH + KBY, kl[0], kl[1], kl[2], kl[3]);
#pragma unroll
                for (int mt = 0; mt < 2; mt++) {
                    mma_bf16(S[mt][ng * 2 + 0], qh[mt], kh[0], kh[1]);
                    mma_bf16(S[mt][ng * 2 + 1], qh[mt], kh[2], kh[3]);
                    mma_bf16(S[mt][ng * 2 + 0], qh[mt], kl[0], kl[1]);
                    mma_bf16(S[mt][ng * 2 + 1], qh[mt], kl[2], kl[3]);
                    mma_bf16(S[mt][ng * 2 + 0], ql[mt], kh[0], kh[1]);
                    mma_bf16(S[mt][ng * 2 + 1], ql[mt], kh[2], kh[3]);
                }
            }
        }

        // ---- fixed-reference softmax
#pragma unroll
        for (int mt = 0; mt < 2; mt++) {
            float s0 = 0.f, s1 = 0.f;
#pragma unroll
            for (int t2 = 0; t2 < 8; t2++) {
                S[mt][t2][0] = ex2f(S[mt][t2][0] * cs);
                S[mt][t2][1] = ex2f(S[mt][t2][1] * cs);
                S[mt][t2][2] = ex2f(S[mt][t2][2] * cs);
                S[mt][t2][3] = ex2f(S[mt][t2][3] * cs);
                s0 += S[mt][t2][0] + S[mt][t2][1];
                s1 += S[mt][t2][2] + S[mt][t2][3];
            }
            ll[mt][0] += s0;
            ll[mt][1] += s1;
        }

        // ---- O += P (Vfh + Vfl)  (fp16, 2 terms)
#pragma unroll
        for (int ks = 0; ks < 4; ks++) {
            uint32_t ph[2][4];
#pragma unroll
            for (int mt = 0; mt < 2; mt++) {
#pragma unroll
                for (int half = 0; half < 2; half++) {
                    int t2 = 2 * ks + half;
                    ph[mt][half * 2 + 0] = h2u(__floats2half2_rn(S[mt][t2][0], S[mt][t2][1]));
                    ph[mt][half * 2 + 1] = h2u(__floats2half2_rn(S[mt][t2][2], S[mt][t2][3]));
                }
            }
#pragma unroll
            for (int dg = 0; dg < 4; dg++) {
                uint32_t vh[4], vl[4];
                uint32_t aH = sb + off + 2 * KBY + (ks * 16 + (g & 1) * 8 + r) * (APAD2 * 2)
                            + (dg * 16 + (g >> 1) * 8) * 2;
                ldsm_x4t(aH, vh[0], vh[1], vh[2], vh[3]);
                ldsm_x4t(aH + KBY, vl[0], vl[1], vl[2], vl[3]);
#pragma unroll
                for (int mt = 0; mt < 2; mt++) {
                    mma_fp16(accO[mt][dg * 2 + 0], ph[mt], vh[0], vh[1]);
                    mma_fp16(accO[mt][dg * 2 + 1], ph[mt], vh[2], vh[3]);
                    mma_fp16(accO[mt][dg * 2 + 0], ph[mt], vl[0], vl[1]);
                    mma_fp16(accO[mt][dg * 2 + 1], ph[mt], vl[2], vl[3]);
                }
            }
        }
    }

    // ---- final l reduction (once)
#pragma unroll
    for (int mt = 0; mt < 2; mt++) {
        ll[mt][0] += __shfl_xor_sync(0xffffffffu, ll[mt][0], 1);
        ll[mt][0] += __shfl_xor_sync(0xffffffffu, ll[mt][0], 2);
        ll[mt][1] += __shfl_xor_sync(0xffffffffu, ll[mt][1], 1);
        ll[mt][1] += __shfl_xor_sync(0xffffffffu, ll[mt][1], 2);
    }

    // ---- epilogue: normalize + split bf16 -> g_Ah/g_Al [b][n][h][d]
#pragma unroll
    for (int mt = 0; mt < 2; mt++) {
        float inv0 = 1.f / ll[mt][0], inv1 = 1.f / ll[mt][1];
        int n_row0 = q0 + wid * 32 + mt * 16 + (lane >> 2);
#pragma unroll
        for (int t2 = 0; t2 < 8; t2++) {
            int col = t2 * 8 + (lane & 3) * 2;
            {
                float o0 = accO[mt][t2][0] * inv0, o1 = accO[mt][t2][1] * inv0;
                __nv_bfloat162 hi = __floats2bfloat162_rn(o0, o1);
                float2 f = __bfloat1622float2(hi);
                __nv_bfloat162 lo = __floats2bfloat162_rn(o0 - f.x, o1 - f.y);
                size_t off = (size_t)(b * SEQ + n_row0) * DM + h * 64 + col;
                *(uint32_t*)&g_Ah[off] = b2u(hi);
                *(uint32_t*)&g_Al[off] = b2u(lo);
            }
            {
                float o0 = accO[mt][t2][2] * inv1, o1 = accO[mt][t2][3] * inv1;
                __nv_bfloat162 hi = __floats2bfloat162_rn(o0, o1);
                float2 f = __bfloat1622float2(hi);
                __nv_bfloat162 lo = __floats2bfloat162_rn(o0 - f.x, o1 - f.y);
                size_t off = (size_t)(b * SEQ + n_row0 + 8) * DM + h * 64 + col;
                *(uint32_t*)&g_Ah[off] = b2u(hi);
                *(uint32_t*)&g_Al[off] = b2u(lo);
            }
        }
    }
}

// ---------------------------------------------------------------------------
extern "C" void kernel_launch(void* const* d_in, const int* in_sizes, int n_in,
                              void* d_out, int out_size)
{
    const float* x     = (const float*)d_in[0];
    const float* pos   = (const float*)d_in[1];
    const float* WQ    = (const float*)d_in[2];
    const float* WK    = (const float*)d_in[3];
    const float* WV    = (const float*)d_in[4];
    const float* WO    = (const float*)d_in[5];
    // d_in[6] = U: unused — qr(U).Q is a complete orthogonal basis, so P = I.
    const float* freqs = (const float*)d_in[7];
    float* out = (float*)d_out;

    cudaFuncSetAttribute(qkv_gemm_mma, cudaFuncAttributeMaxDynamicSharedMemorySize, GEMM_SMEM);
    cudaFuncSetAttribute(out_gemm_mma, cudaFuncAttributeMaxDynamicSharedMemorySize, GEMM_SMEM);
    cudaFuncSetAttribute(attn_mma_kernel, cudaFuncAttributeMaxDynamicSharedMemorySize, ATTN_SMEM);

    // 0. fused prep: x split + cs table + weight transpose/split
    prep_kernel<<<3072, 256>>>(x, pos, freqs, WQ, WK, WV, WO);
    // 1. fused QKV projection + RoPE + split (64x128 tiles, 768 blocks)
    qkv_gemm_mma<<<dim3(12, 64), 128, GEMM_SMEM>>>();
    // 2. flash attention (bf16 S, fp16 PV, fixed-ref softmax)
    attn_mma_kernel<<<dim3(SEQ / 128, BATCH * NH), 128, ATTN_SMEM>>>();
    // 3. output projection (64x128 tiles, 256 blocks)
    out_gemm_mma<<<dim3(4, 64), 128, GEMM_SMEM>>>(out);
}

// round 15
// speedup vs baseline: 1.0178x; 1.0178x over previous
#include <cuda_runtime.h>
#include <cuda_bf16.h>
#include <cuda_fp16.h>
#include <math.h>
#include <stdint.h>

// Problem constants
#define BATCH 4
#define SEQ   1024
#define DM    512
#define NH    8
#define DH    64
#define ROWS  (BATCH*SEQ)          // 4096

// ---------------------------------------------------------------------------
// Scratch (__device__ globals: allocation-free rule)
// ---------------------------------------------------------------------------
__device__ __nv_bfloat16 g_xh[ROWS*DM];     // x split hi
__device__ __nv_bfloat16 g_xl[ROWS*DM];     // x split lo
__device__ __nv_bfloat16 g_Ah[ROWS*DM];     // attention out split hi [b][n][h][d]
__device__ __nv_bfloat16 g_Al[ROWS*DM];     // attention out split lo
// Transposed weights (n-major rows), bf16 split:
// rows 0..1535 = WQ|WK|WV, rows 1536..2047 = WO
__device__ __nv_bfloat16 g_Wth[2048*512];
__device__ __nv_bfloat16 g_Wtl[2048*512];
// Attention-layout splits: [b][h][n][d]
#define BHND (32*1024*64)
__device__ __nv_bfloat16 g_Qbh[BHND], g_Qbl[BHND];   // Q bf16 hi/lo
__device__ __nv_bfloat16 g_Kbh[BHND], g_Kbl[BHND];   // K bf16 hi/lo
__device__ __half        g_Vfh[BHND], g_Vfl[BHND];   // V fp16 hi/lo
// RoPE cos/sin table: [h][n][m] -> float2 (cos, sin)
__device__ float2 g_cs[NH*SEQ*32];

// ---------------------------------------------------------------------------
// Helpers
// ---------------------------------------------------------------------------
__device__ __forceinline__ uint32_t smem_u32(const void* p) {
    uint32_t a;
    asm("{ .reg .u64 t; cvta.to.shared.u64 t, %1; cvt.u32.u64 %0, t; }" : "=r"(a) : "l"(p));
    return a;
}
__device__ __forceinline__ void ldsm_x4(uint32_t addr, uint32_t& r0, uint32_t& r1,
                                        uint32_t& r2, uint32_t& r3) {
    asm volatile("ldmatrix.sync.aligned.m8n8.x4.shared.b16 {%0,%1,%2,%3}, [%4];"
                 : "=r"(r0), "=r"(r1), "=r"(r2), "=r"(r3) : "r"(addr));
}
__device__ __forceinline__ void ldsm_x4t(uint32_t addr, uint32_t& r0, uint32_t& r1,
                                         uint32_t& r2, uint32_t& r3) {
    asm volatile("ldmatrix.sync.aligned.m8n8.x4.trans.shared.b16 {%0,%1,%2,%3}, [%4];"
                 : "=r"(r0), "=r"(r1), "=r"(r2), "=r"(r3) : "r"(addr));
}
__device__ __forceinline__ void mma_bf16(float* c, const uint32_t* a,
                                         uint32_t b0, uint32_t b1) {
    asm volatile(
        "mma.sync.aligned.m16n8k16.row.col.f32.bf16.bf16.f32 "
        "{%0,%1,%2,%3}, {%4,%5,%6,%7}, {%8,%9}, {%0,%1,%2,%3};"
        : "+f"(c[0]), "+f"(c[1]), "+f"(c[2]), "+f"(c[3])
        : "r"(a[0]), "r"(a[1]), "r"(a[2]), "r"(a[3]), "r"(b0), "r"(b1));
}
__device__ __forceinline__ void mma_fp16(float* c, const uint32_t* a,
                                         uint32_t b0, uint32_t b1) {
    asm volatile(
        "mma.sync.aligned.m16n8k16.row.col.f32.f16.f16.f32 "
        "{%0,%1,%2,%3}, {%4,%5,%6,%7}, {%8,%9}, {%0,%1,%2,%3};"
        : "+f"(c[0]), "+f"(c[1]), "+f"(c[2]), "+f"(c[3])
        : "r"(a[0]), "r"(a[1]), "r"(a[2]), "r"(a[3]), "r"(b0), "r"(b1));
}
__device__ __forceinline__ float ex2f(float x) {
    float y;
    asm("ex2.approx.f32 %0, %1;" : "=f"(y) : "f"(x));
    return y;
}
__device__ __forceinline__ uint32_t b2u(__nv_bfloat162 v) {
    return *reinterpret_cast<uint32_t*>(&v);
}
__device__ __forceinline__ uint32_t h2u(__half2 v) {
    return *reinterpret_cast<uint32_t*>(&v);
}
__device__ __forceinline__ void cp16(uint32_t dst, const void* src) {
    asm volatile("cp.async.cg.shared.global [%0], [%1], 16;" :: "r"(dst), "l"(src));
}
#define CP_COMMIT() asm volatile("cp.async.commit_group;" ::: "memory")
#define CP_WAIT1()  asm volatile("cp.async.wait_group 1;" ::: "memory")
#define CP_WAIT0()  asm volatile("cp.async.wait_group 0;" ::: "memory")

// ---------------------------------------------------------------------------
// Fused prep kernel
// ---------------------------------------------------------------------------
__global__ void prep_kernel(const float* __restrict__ x,
                            const float* __restrict__ pos,
                            const float* __restrict__ freqs,
                            const float* __restrict__ WQ,
                            const float* __restrict__ WK,
                            const float* __restrict__ WV,
                            const float* __restrict__ WO) {
    const int bid = blockIdx.x;
    if (bid < 2048) {
        int i = bid * 256 + threadIdx.x;
        float4 v = ((const float4*)x)[i];
        float vv[4] = {v.x, v.y, v.z, v.w};
#pragma unroll
        for (int j = 0; j < 4; j++) {
            __nv_bfloat16 h = __float2bfloat16(vv[j]);
            __nv_bfloat16 l = __float2bfloat16(vv[j] - __bfloat162float(h));
            g_xh[4 * i + j] = h;
            g_xl[4 * i + j] = l;
        }
        if (i < NH * SEQ * 32) {
            int m = i & 31;
            int n = (i >> 5) & 1023;
            int h = i >> 15;
            float ang = pos[n * 2 + 0] * freqs[(h * 32 + m) * 2 + 0]
                      + pos[n * 2 + 1] * freqs[(h * 32 + m) * 2 + 1];
            float s, c;
            sincosf(ang, &s, &c);
            g_cs[i] = make_float2(c, s);
        }
    } else {
        __shared__ float t[32][33];
        const int wb = bid - 2048;          // 0..1023
        const int z  = wb >> 8;             // 0..3
        const float* W = (z == 0) ? WQ : (z == 1) ? WK : (z == 2) ? WV : WO;
        const int zoff = z * 512;
        const int rest = wb & 255;
        const int k0 = (rest & 15) * 32, n0 = (rest >> 4) * 32;
        const int tx = threadIdx.x & 31, ty = threadIdx.x >> 5;   // 32 x 8
#pragma unroll
        for (int i = 0; i < 4; i++)
            t[ty + i * 8][tx] = W[(k0 + ty + i * 8) * 512 + n0 + tx];
        __syncthreads();
#pragma unroll
        for (int i = 0; i < 4; i++) {
            float v = t[tx][ty + i * 8];
            __nv_bfloat16 h = __float2bfloat16(v);
            __nv_bfloat16 l = __float2bfloat16(v - __bfloat162float(h));
            int dst = (zoff + n0 + ty + i * 8) * 512 + k0 + tx;
            g_Wth[dst] = h;
            g_Wtl[dst] = l;
        }
    }
}

// ---------------------------------------------------------------------------
// Split-bf16 GEMM: block tile 128x128, BK=32, 8 warps (2m x 4n), warp 64x32.
// Stage layout: [A_h | A_l | B_h | B_l], each 128 x APAD bf16.
// gemm_core  : 2-stage pipeline (for qkv: 2 blocks/SM give cross-block overlap)
// gemm_core3 : 3-stage pipeline (for out: 128 blocks, 1/SM, needs deep prefetch)
// ---------------------------------------------------------------------------
#define APAD 40
#define ABY  (128*APAD*2)    // 10240 B per array
#define GBUF (4*ABY)         // 40960 B per stage
#define GEMM_SMEM  (2*GBUF)  // 81920 B
#define GEMM_SMEM3 (3*GBUF)  // 122880 B

struct GemmFrag { float acc[4][4][4]; };

// Shared compute body for one 32-wide K chunk at smem stage offset `off`.
__device__ __forceinline__ void gemm_chunk(
    uint32_t aBH, uint32_t aBL, uint32_t bBH, uint32_t bBL,
    uint32_t off, GemmFrag& fr)
{
#pragma unroll
    for (int ks = 0; ks < 2; ks++) {
        const uint32_t koff = off + ks * 32;
        uint32_t ah[4][4], al[4][4], bh[2][4], bl[2][4];
#pragma unroll
        for (int mt = 0; mt < 4; mt++) {
            ldsm_x4(aBH + mt * (16 * APAD * 2) + koff, ah[mt][0], ah[mt][1], ah[mt][2], ah[mt][3]);
            ldsm_x4(aBL + mt * (16 * APAD * 2) + koff, al[mt][0], al[mt][1], al[mt][2], al[mt][3]);
        }
#pragma unroll
        for (int nt = 0; nt < 2; nt++) {
            ldsm_x4(bBH + nt * (16 * APAD * 2) + koff, bh[nt][0], bh[nt][1], bh[nt][2], bh[nt][3]);
            ldsm_x4(bBL + nt * (16 * APAD * 2) + koff, bl[nt][0], bl[nt][1], bl[nt][2], bl[nt][3]);
        }
#pragma unroll
        for (int mt = 0; mt < 4; mt++)
#pragma unroll
            for (int ng = 0; ng < 4; ng++) {
                const int nt = ng >> 1, p = (ng & 1) * 2;
                mma_bf16(fr.acc[mt][ng], ah[mt], bh[nt][p], bh[nt][p + 1]);
                mma_bf16(fr.acc[mt][ng], ah[mt], bl[nt][p], bl[nt][p + 1]);
                mma_bf16(fr.acc[mt][ng], al[mt], bh[nt][p], bh[nt][p + 1]);
            }
    }
}

__device__ __forceinline__ void gemm_core(
    const __nv_bfloat16* __restrict__ Ah, const __nv_bfloat16* __restrict__ Al,
    const __nv_bfloat16* __restrict__ Bh, const __nv_bfloat16* __restrict__ Bl,
    GemmFrag& fr)
{
    extern __shared__ char sm[];
    const uint32_t sb = smem_u32(sm);
    const int tid  = threadIdx.x;
    const int wid  = tid >> 5, lane = tid & 31;
    const int wm   = wid >> 2, wn = wid & 3;
    const int g    = lane >> 3, r = lane & 7;

#pragma unroll
    for (int i = 0; i < 4; i++)
#pragma unroll
        for (int j = 0; j < 4; j++)
#pragma unroll
            for (int k = 0; k < 4; k++) fr.acc[i][j][k] = 0.f;

    const int c0row = tid >> 2, c0cb = tid & 3;
    const int c1row = (tid + 256) >> 2;
    const uint32_t d0 = sb + c0row * (APAD * 2) + c0cb * 16;
    const uint32_t d1 = sb + c1row * (APAD * 2) + c0cb * 16;
    const size_t s0 = (size_t)c0row * 512 + c0cb * 8;
    const size_t s1 = (size_t)c1row * 512 + c0cb * 8;

    const uint32_t aBH = sb + (wm * 64 + (g & 1) * 8 + r) * (APAD * 2) + ((g >> 1) * 8) * 2;
    const uint32_t aBL = aBH + ABY;
    const uint32_t bBH = sb + 2 * ABY + (wn * 32 + (g >> 1) * 8 + r) * (APAD * 2) + ((g & 1) * 8) * 2;
    const uint32_t bBL = bBH + ABY;

    {
        cp16(d0 + 0 * ABY, Ah + s0); cp16(d1 + 0 * ABY, Ah + s1);
        cp16(d0 + 1 * ABY, Al + s0); cp16(d1 + 1 * ABY, Al + s1);
        cp16(d0 + 2 * ABY, Bh + s0); cp16(d1 + 2 * ABY, Bh + s1);
        cp16(d0 + 3 * ABY, Bl + s0); cp16(d1 + 3 * ABY, Bl + s1);
        CP_COMMIT();
    }

#pragma unroll 1
    for (int kc = 0; kc < 16; kc++) {
        CP_WAIT0();
        __syncthreads();
        if (kc < 15) {
            const int k1 = (kc + 1) * 32;
            const uint32_t off = ((kc + 1) & 1) * GBUF;
            cp16(d0 + off + 0 * ABY, Ah + s0 + k1); cp16(d1 + off + 0 * ABY, Ah + s1 + k1);
            cp16(d0 + off + 1 * ABY, Al + s0 + k1); cp16(d1 + off + 1 * ABY, Al + s1 + k1);
            cp16(d0 + off + 2 * ABY, Bh + s0 + k1); cp16(d1 + off + 2 * ABY, Bh + s1 + k1);
            cp16(d0 + off + 3 * ABY, Bl + s0 + k1); cp16(d1 + off + 3 * ABY, Bl + s1 + k1);
            CP_COMMIT();
        }
        gemm_chunk(aBH, aBL, bBH, bBL, (kc & 1) * GBUF, fr);
    }
}

// 3-stage variant: prefetch distance 2.
__device__ __forceinline__ void gemm_core3(
    const __nv_bfloat16* __restrict__ Ah, const __nv_bfloat16* __restrict__ Al,
    const __nv_bfloat16* __restrict__ Bh, const __nv_bfloat16* __restrict__ Bl,
    GemmFrag& fr)
{
    extern __shared__ char sm[];
    const uint32_t sb = smem_u32(sm);
    const int tid  = threadIdx.x;
    const int wid  = tid >> 5, lane = tid & 31;
    const int wm   = wid >> 2, wn = wid & 3;
    const int g    = lane >> 3, r = lane & 7;

#pragma unroll
    for (int i = 0; i < 4; i++)
#pragma unroll
        for (int j = 0; j < 4; j++)
#pragma unroll
            for (int k = 0; k < 4; k++) fr.acc[i][j][k] = 0.f;

    const int c0row = tid >> 2, c0cb = tid & 3;
    const int c1row = (tid + 256) >> 2;
    const uint32_t d0 = sb + c0row * (APAD * 2) + c0cb * 16;
    const uint32_t d1 = sb + c1row * (APAD * 2) + c0cb * 16;
    const size_t s0 = (size_t)c0row * 512 + c0cb * 8;
    const size_t s1 = (size_t)c1row * 512 + c0cb * 8;

    const uint32_t aBH = sb + (wm * 64 + (g & 1) * 8 + r) * (APAD * 2) + ((g >> 1) * 8) * 2;
    const uint32_t aBL = aBH + ABY;
    const uint32_t bBH = sb + 2 * ABY + (wn * 32 + (g >> 1) * 8 + r) * (APAD * 2) + ((g & 1) * 8) * 2;
    const uint32_t bBL = bBH + ABY;

    // prologue: stage chunks 0 and 1 (separate commit groups)
#pragma unroll
    for (int s = 0; s < 2; s++) {
        const int k1 = s * 32;
        const uint32_t off = s * GBUF;
        cp16(d0 + off + 0 * ABY, Ah + s0 + k1); cp16(d1 + off + 0 * ABY, Ah + s1 + k1);
        cp16(d0 + off + 1 * ABY, Al + s0 + k1); cp16(d1 + off + 1 * ABY, Al + s1 + k1);
        cp16(d0 + off + 2 * ABY, Bh + s0 + k1); cp16(d1 + off + 2 * ABY, Bh + s1 + k1);
        cp16(d0 + off + 3 * ABY, Bl + s0 + k1); cp16(d1 + off + 3 * ABY, Bl + s1 + k1);
        CP_COMMIT();
    }

#pragma unroll 1
    for (int kc = 0; kc < 16; kc++) {
        if (kc < 15) { CP_WAIT1(); } else { CP_WAIT0(); }
        __syncthreads();
        if (kc < 14) {
            const int k1 = (kc + 2) * 32;
            const uint32_t off = ((kc + 2) % 3) * GBUF;
            cp16(d0 + off + 0 * ABY, Ah + s0 + k1); cp16(d1 + off + 0 * ABY, Ah + s1 + k1);
            cp16(d0 + off + 1 * ABY, Al + s0 + k1); cp16(d1 + off + 1 * ABY, Al + s1 + k1);
            cp16(d0 + off + 2 * ABY, Bh + s0 + k1); cp16(d1 + off + 2 * ABY, Bh + s1 + k1);
            cp16(d0 + off + 3 * ABY, Bl + s0 + k1); cp16(d1 + off + 3 * ABY, Bl + s1 + k1);
            CP_COMMIT();
        }
        gemm_chunk(aBH, aBL, bBH, bBL, (kc % 3) * GBUF, fr);
    }
}

// QKV projection: grid (12, 32), 256 threads. Fused RoPE + split epilogue.
__global__ void __launch_bounds__(256) qkv_gemm_mma() {
    const int gn0 = blockIdx.x * 128;
    const int sel = gn0 >> 9;
    const int hb  = (gn0 >> 6) & 7;
    const int m0  = blockIdx.y * 128;

    GemmFrag fr;
    gemm_core(g_xh + (size_t)m0 * 512, g_xl + (size_t)m0 * 512,
              g_Wth + (size_t)gn0 * 512, g_Wtl + (size_t)gn0 * 512, fr);

    const int wid = threadIdx.x >> 5, lane = threadIdx.x & 31;
    const int wm = wid >> 2, wn = wid & 3;

#pragma unroll
    for (int mt = 0; mt < 4; mt++) {
        int row0 = wm * 64 + mt * 16 + (lane >> 2);
#pragma unroll
        for (int ng = 0; ng < 4; ng++) {
            int col = wn * 32 + ng * 8 + (lane & 3) * 2;
            int h2 = hb + (col >> 6);
            int hd = col & 63;
            float v0 = fr.acc[mt][ng][0], v1 = fr.acc[mt][ng][1];
            float v2 = fr.acc[mt][ng][2], v3 = fr.acc[mt][ng][3];
            int tok0 = m0 + row0, tok1 = tok0 + 8;
            size_t off0 = ((size_t)((tok0 >> 10) * 8 + h2) * 1024 + (tok0 & 1023)) * 64 + hd;
            size_t off1 = ((size_t)((tok1 >> 10) * 8 + h2) * 1024 + (tok1 & 1023)) * 64 + hd;
            if (sel == 2) {
                __half2 hi0 = __floats2half2_rn(v0, v1);
                __half2 hi1 = __floats2half2_rn(v2, v3);
                float2 f0 = __half22float2(hi0);
                float2 f1 = __half22float2(hi1);
                __half2 lo0 = __floats2half2_rn(v0 - f0.x, v1 - f0.y);
                __half2 lo1 = __floats2half2_rn(v2 - f1.x, v3 - f1.y);
                *(uint32_t*)&g_Vfh[off0] = h2u(hi0);
                *(uint32_t*)&g_Vfl[off0] = h2u(lo0);
                *(uint32_t*)&g_Vfh[off1] = h2u(hi1);
                *(uint32_t*)&g_Vfl[off1] = h2u(lo1);
            } else {
                int mp = hd >> 1;
                float2 cs0 = g_cs[(h2 * 1024 + (tok0 & 1023)) * 32 + mp];
                float2 cs1 = g_cs[(h2 * 1024 + (tok1 & 1023)) * 32 + mp];
                float a0 = v0, b0 = v1;
                v0 = a0 * cs0.x - b0 * cs0.y;
                v1 = a0 * cs0.y + b0 * cs0.x;
                float a1 = v2, b1 = v3;
                v2 = a1 * cs1.x - b1 * cs1.y;
                v3 = a1 * cs1.y + b1 * cs1.x;
                __nv_bfloat16* Dh = (sel == 0) ? g_Qbh : g_Kbh;
                __nv_bfloat16* Dl = (sel == 0) ? g_Qbl : g_Kbl;
                __nv_bfloat162 hi0 = __floats2bfloat162_rn(v0, v1);
                __nv_bfloat162 hi1 = __floats2bfloat162_rn(v2, v3);
                float2 f0 = __bfloat1622float2(hi0);
                float2 f1 = __bfloat1622float2(hi1);
                __nv_bfloat162 lo0 = __floats2bfloat162_rn(v0 - f0.x, v1 - f0.y);
                __nv_bfloat162 lo1 = __floats2bfloat162_rn(v2 - f1.x, v3 - f1.y);
                *(uint32_t*)&Dh[off0] = b2u(hi0);
                *(uint32_t*)&Dl[off0] = b2u(lo0);
                *(uint32_t*)&Dh[off1] = b2u(hi1);
                *(uint32_t*)&Dl[off1] = b2u(lo1);
            }
        }
    }
}

// Output projection: grid (4, 32), 256 threads, 3-stage pipeline.
__global__ void __launch_bounds__(256) out_gemm_mma(float* __restrict__ out) {
    const int n0 = blockIdx.x * 128;
    const int m0 = blockIdx.y * 128;
    GemmFrag fr;
    gemm_core3(g_Ah + (size_t)m0 * 512, g_Al + (size_t)m0 * 512,
               g_Wth + (size_t)(1536 + n0) * 512, g_Wtl + (size_t)(1536 + n0) * 512, fr);

    const int wid = threadIdx.x >> 5, lane = threadIdx.x & 31;
    const int wm = wid >> 2, wn = wid & 3;
    float* C = out + (size_t)m0 * 512 + n0;
#pragma unroll
    for (int mt = 0; mt < 4; mt++) {
        int row0 = wm * 64 + mt * 16 + (lane >> 2);
#pragma unroll
        for (int ng = 0; ng < 4; ng++) {
            int col = wn * 32 + ng * 8 + (lane & 3) * 2;
            *(float2*)(C + (size_t)row0 * 512 + col) =
                make_float2(fr.acc[mt][ng][0], fr.acc[mt][ng][1]);
            *(float2*)(C + (size_t)(row0 + 8) * 512 + col) =
                make_float2(fr.acc[mt][ng][2], fr.acc[mt][ng][3]);
        }
    }
}

// ---------------------------------------------------------------------------
// Tensor-core flash attention (R13 config):
//   S = 3-term split-bf16; O = fp16 P x (Vfh + Vfl)
// Fixed-reference softmax, Q persistent in smem, cp.async double-buffered
// K/V with one barrier per key block. Stage = [Kh | Kl | Vfh | Vfl].
// ---------------------------------------------------------------------------
#define APAD2 72
#define KBY   (64*APAD2*2)     // 9216 B per array
#define KBUF  (4*KBY)          // 36864 B per stage
#define QOFF  (2*KBUF)         // 73728
#define QBY   (128*APAD2*2)    // 18432 B per Q array
#define ATTN_SMEM (QOFF + 2*QBY)   // 110592 B

__global__ void __launch_bounds__(128) attn_mma_kernel()
{
    extern __shared__ char sm[];
    const uint32_t sb = smem_u32(sm);

    const int bh = blockIdx.y;
    const int b = bh >> 3, h = bh & 7;
    const int q0 = blockIdx.x * 128;
    const int tid = threadIdx.x, wid = tid >> 5, lane = tid & 31;
    const int g = lane >> 3, r = lane & 7;
    const float cs = 0.25500300f;    // (1/sqrt(32)) * log2(e)

    const size_t base = (size_t)bh * SEQ * 64;
    const __nv_bfloat16* Qh = g_Qbh + base + (size_t)q0 * 64;
    const __nv_bfloat16* Ql = g_Qbl + base + (size_t)q0 * 64;
    const __nv_bfloat16* Kh = g_Kbh + base;
    const __nv_bfloat16* Kl = g_Kbl + base;
    const __half*        Vh = g_Vfh + base;
    const __half*        Vl = g_Vfl + base;

    uint32_t e[4];
    size_t t[4];
#pragma unroll
    for (int u = 0; u < 4; u++) {
        int idx = u * 128 + tid;
        e[u] = sb + (idx >> 3) * (APAD2 * 2) + (idx & 7) * 16;
        t[u] = (size_t)(idx >> 3) * 64 + (idx & 7) * 8;
    }

#pragma unroll
    for (int u = 0; u < 8; u++) {
        int idx = u * 128 + tid;
        uint32_t dst = sb + QOFF + (idx >> 3) * (APAD2 * 2) + (idx & 7) * 16;
        size_t src = (size_t)(idx >> 3) * 64 + (idx & 7) * 8;
        cp16(dst, Qh + src);
        cp16(dst + QBY, Ql + src);
    }
#pragma unroll
    for (int u = 0; u < 4; u++) {
        cp16(e[u] + 0 * KBY, Kh + t[u]);
        cp16(e[u] + 1 * KBY, Kl + t[u]);
        cp16(e[u] + 2 * KBY, Vh + t[u]);
        cp16(e[u] + 3 * KBY, Vl + t[u]);
    }
    CP_COMMIT();

    float accO[2][8][4];
#pragma unroll
    for (int mt = 0; mt < 2; mt++)
#pragma unroll
        for (int t2 = 0; t2 < 8; t2++)
#pragma unroll
            for (int j = 0; j < 4; j++) accO[mt][t2][j] = 0.f;
    float ll[2][2];
#pragma unroll
    for (int mt = 0; mt < 2; mt++) { ll[mt][0] = 0.f; ll[mt][1] = 0.f; }

#pragma unroll 1
    for (int kb = 0; kb < 16; kb++) {
        CP_WAIT0();
        __syncthreads();
        if (kb < 15) {
            const size_t koff = (size_t)(kb + 1) * 64 * 64;
            const uint32_t off = ((kb + 1) & 1) * KBUF;
#pragma unroll
            for (int u = 0; u < 4; u++) {
                cp16(e[u] + off + 0 * KBY, Kh + koff + t[u]);
                cp16(e[u] + off + 1 * KBY, Kl + koff + t[u]);
                cp16(e[u] + off + 2 * KBY, Vh + koff + t[u]);
                cp16(e[u] + off + 3 * KBY, Vl + koff + t[u]);
            }
            CP_COMMIT();
        }
        const uint32_t off = (kb & 1) * KBUF;

        // ---- S = Q K^T (split-bf16, 3 terms)
        float S[2][8][4];
#pragma unroll
        for (int mt = 0; mt < 2; mt++)
#pragma unroll
            for (int t2 = 0; t2 < 8; t2++)
#pragma unroll
                for (int j = 0; j < 4; j++) S[mt][t2][j] = 0.f;
#pragma unroll
        for (int ks = 0; ks < 4; ks++) {
            uint32_t qh[2][4], ql[2][4];
#pragma unroll
            for (int mt = 0; mt < 2; mt++) {
                uint32_t qa = sb + QOFF
                            + (wid * 32 + mt * 16 + (g & 1) * 8 + r) * (APAD2 * 2)
                            + (ks * 16 + (g >> 1) * 8) * 2;
                ldsm_x4(qa, qh[mt][0], qh[mt][1], qh[mt][2], qh[mt][3]);
                ldsm_x4(qa + QBY, ql[mt][0], ql[mt][1], ql[mt][2], ql[mt][3]);
            }
#pragma unroll
            for (int ng = 0; ng < 4; ng++) {
                uint32_t kh[4], kl[4];
                uint32_t aH = sb + off + (ng * 16 + (g >> 1) * 8 + r) * (APAD2 * 2)
                            + (ks * 16 + (g & 1) * 8) * 2;
                ldsm_x4(aH, kh[0], kh[1], kh[2], kh[3]);
                ldsm_x4(aH + KBY, kl[0], kl[1], kl[2], kl[3]);
#pragma unroll
                for (int mt = 0; mt < 2; mt++) {
                    mma_bf16(S[mt][ng * 2 + 0], qh[mt], kh[0], kh[1]);
                    mma_bf16(S[mt][ng * 2 + 1], qh[mt], kh[2], kh[3]);
                    mma_bf16(S[mt][ng * 2 + 0], qh[mt], kl[0], kl[1]);
                    mma_bf16(S[mt][ng * 2 + 1], qh[mt], kl[2], kl[3]);
                    mma_bf16(S[mt][ng * 2 + 0], ql[mt], kh[0], kh[1]);
                    mma_bf16(S[mt][ng * 2 + 1], ql[mt], kh[2], kh[3]);
                }
            }
        }

        // ---- fixed-reference softmax
#pragma unroll
        for (int mt = 0; mt < 2; mt++) {
            float s0 = 0.f, s1 = 0.f;
#pragma unroll
            for (int t2 = 0; t2 < 8; t2++) {
                S[mt][t2][0] = ex2f(S[mt][t2][0] * cs);
                S[mt][t2][1] = ex2f(S[mt][t2][1] * cs);
                S[mt][t2][2] = ex2f(S[mt][t2][2] * cs);
                S[mt][t2][3] = ex2f(S[mt][t2][3] * cs);
                s0 += S[mt][t2][0] + S[mt][t2][1];
                s1 += S[mt][t2][2] + S[mt][t2][3];
            }
            ll[mt][0] += s0;
            ll[mt][1] += s1;
        }

        // ---- O += P (Vfh + Vfl)  (fp16, 2 terms)
#pragma unroll
        for (int ks = 0; ks < 4; ks++) {
            uint32_t ph[2][4];
#pragma unroll
            for (int mt = 0; mt < 2; mt++) {
#pragma unroll
                for (int half = 0; half < 2; half++) {
                    int t2 = 2 * ks + half;
                    ph[mt][half * 2 + 0] = h2u(__floats2half2_rn(S[mt][t2][0], S[mt][t2][1]));
                    ph[mt][half * 2 + 1] = h2u(__floats2half2_rn(S[mt][t2][2], S[mt][t2][3]));
                }
            }
#pragma unroll
            for (int dg = 0; dg < 4; dg++) {
                uint32_t vh[4], vl[4];
                uint32_t aH = sb + off + 2 * KBY + (ks * 16 + (g & 1) * 8 + r) * (APAD2 * 2)
                            + (dg * 16 + (g >> 1) * 8) * 2;
                ldsm_x4t(aH, vh[0], vh[1], vh[2], vh[3]);
                ldsm_x4t(aH + KBY, vl[0], vl[1], vl[2], vl[3]);
#pragma unroll
                for (int mt = 0; mt < 2; mt++) {
                    mma_fp16(accO[mt][dg * 2 + 0], ph[mt], vh[0], vh[1]);
                    mma_fp16(accO[mt][dg * 2 + 1], ph[mt], vh[2], vh[3]);
                    mma_fp16(accO[mt][dg * 2 + 0], ph[mt], vl[0], vl[1]);
                    mma_fp16(accO[mt][dg * 2 + 1], ph[mt], vl[2], vl[3]);
                }
            }
        }
    }

    // ---- final l reduction (once)
#pragma unroll
    for (int mt = 0; mt < 2; mt++) {
        ll[mt][0] += __shfl_xor_sync(0xffffffffu, ll[mt][0], 1);
        ll[mt][0] += __shfl_xor_sync(0xffffffffu, ll[mt][0], 2);
        ll[mt][1] += __shfl_xor_sync(0xffffffffu, ll[mt][1], 1);
        ll[mt][1] += __shfl_xor_sync(0xffffffffu, ll[mt][1], 2);
    }

    // ---- epilogue: normalize + split bf16 -> g_Ah/g_Al [b][n][h][d]
#pragma unroll
    for (int mt = 0; mt < 2; mt++) {
        float inv0 = 1.f / ll[mt][0], inv1 = 1.f / ll[mt][1];
        int n_row0 = q0 + wid * 32 + mt * 16 + (lane >> 2);
#pragma unroll
        for (int t2 = 0; t2 < 8; t2++) {
            int col = t2 * 8 + (lane & 3) * 2;
            {
                float o0 = accO[mt][t2][0] * inv0, o1 = accO[mt][t2][1] * inv0;
                __nv_bfloat162 hi = __floats2bfloat162_rn(o0, o1);
                float2 f = __bfloat1622float2(hi);
                __nv_bfloat162 lo = __floats2bfloat162_rn(o0 - f.x, o1 - f.y);
                size_t off = (size_t)(b * SEQ + n_row0) * DM + h * 64 + col;
                *(uint32_t*)&g_Ah[off] = b2u(hi);
                *(uint32_t*)&g_Al[off] = b2u(lo);
            }
            {
                float o0 = accO[mt][t2][2] * inv1, o1 = accO[mt][t2][3] * inv1;
                __nv_bfloat162 hi = __floats2bfloat162_rn(o0, o1);
                float2 f = __bfloat1622float2(hi);
                __nv_bfloat162 lo = __floats2bfloat162_rn(o0 - f.x, o1 - f.y);
                size_t off = (size_t)(b * SEQ + n_row0 + 8) * DM + h * 64 + col;
                *(uint32_t*)&g_Ah[off] = b2u(hi);
                *(uint32_t*)&g_Al[off] = b2u(lo);
            }
        }
    }
}

// ---------------------------------------------------------------------------
extern "C" void kernel_launch(void* const* d_in, const int* in_sizes, int n_in,
                              void* d_out, int out_size)
{
    const float* x     = (const float*)d_in[0];
    const float* pos   = (const float*)d_in[1];
    const float* WQ    = (const float*)d_in[2];
    const float* WK    = (const float*)d_in[3];
    const float* WV    = (const float*)d_in[4];
    const float* WO    = (const float*)d_in[5];
    // d_in[6] = U: unused — qr(U).Q is a complete orthogonal basis, so P = I.
    const float* freqs = (const float*)d_in[7];
    float* out = (float*)d_out;

    cudaFuncSetAttribute(qkv_gemm_mma, cudaFuncAttributeMaxDynamicSharedMemorySize, GEMM_SMEM);
    cudaFuncSetAttribute(out_gemm_mma, cudaFuncAttributeMaxDynamicSharedMemorySize, GEMM_SMEM3);
    cudaFuncSetAttribute(attn_mma_kernel, cudaFuncAttributeMaxDynamicSharedMemorySize, ATTN_SMEM);

    // 0. fused prep: x split + cs table + weight transpose/split
    prep_kernel<<<3072, 256>>>(x, pos, freqs, WQ, WK, WV, WO);
    // 1. fused QKV projection + RoPE + split (128x128 tiles, 2-stage)
    qkv_gemm_mma<<<dim3(12, 32), 256, GEMM_SMEM>>>();
    // 2. flash attention (bf16 S, fp16 PV, fixed-ref softmax)
    attn_mma_kernel<<<dim3(SEQ / 128, BATCH * NH), 128, ATTN_SMEM>>>();
    // 3. output projection (128x128 tiles, 3-stage pipeline)
    out_gemm_mma<<<dim3(4, 32), 256, GEMM_SMEM3>>>(out);
}

// round 16
// speedup vs baseline: 1.0960x; 1.0768x over previous
#include <cuda_runtime.h>
#include <cuda_bf16.h>
#include <cuda_fp16.h>
#include <math.h>
#include <stdint.h>

// Problem constants
#define BATCH 4
#define SEQ   1024
#define DM    512
#define NH    8
#define DH    64
#define ROWS  (BATCH*SEQ)          // 4096

// ---------------------------------------------------------------------------
// Scratch (__device__ globals: allocation-free rule)
// ---------------------------------------------------------------------------
__device__ __nv_bfloat16 g_xh[ROWS*DM];     // x split hi
__device__ __nv_bfloat16 g_xl[ROWS*DM];     // x split lo
__device__ __nv_bfloat16 g_Ah[ROWS*DM];     // attention out split hi [b][n][h][d]
__device__ __nv_bfloat16 g_Al[ROWS*DM];     // attention out split lo
// Transposed weights (n-major rows), bf16 split:
// rows 0..1535 = WQ|WK|WV, rows 1536..2047 = WO
__device__ __nv_bfloat16 g_Wth[2048*512];
__device__ __nv_bfloat16 g_Wtl[2048*512];
// Attention-layout splits: [b][h][n][d]
#define BHND (32*1024*64)
__device__ __nv_bfloat16 g_Qbh[BHND], g_Qbl[BHND];   // Q bf16 hi/lo
__device__ __nv_bfloat16 g_Kbh[BHND], g_Kbl[BHND];   // K bf16 hi/lo
__device__ __half        g_Vfh[BHND];                // V fp16 (single)
// RoPE cos/sin table: [h][n][m] -> float2 (cos, sin)
__device__ float2 g_cs[NH*SEQ*32];

// ---------------------------------------------------------------------------
// Helpers
// ---------------------------------------------------------------------------
__device__ __forceinline__ uint32_t smem_u32(const void* p) {
    uint32_t a;
    asm("{ .reg .u64 t; cvta.to.shared.u64 t, %1; cvt.u32.u64 %0, t; }" : "=r"(a) : "l"(p));
    return a;
}
__device__ __forceinline__ void ldsm_x4(uint32_t addr, uint32_t& r0, uint32_t& r1,
                                        uint32_t& r2, uint32_t& r3) {
    asm volatile("ldmatrix.sync.aligned.m8n8.x4.shared.b16 {%0,%1,%2,%3}, [%4];"
                 : "=r"(r0), "=r"(r1), "=r"(r2), "=r"(r3) : "r"(addr));
}
__device__ __forceinline__ void ldsm_x4t(uint32_t addr, uint32_t& r0, uint32_t& r1,
                                         uint32_t& r2, uint32_t& r3) {
    asm volatile("ldmatrix.sync.aligned.m8n8.x4.trans.shared.b16 {%0,%1,%2,%3}, [%4];"
                 : "=r"(r0), "=r"(r1), "=r"(r2), "=r"(r3) : "r"(addr));
}
__device__ __forceinline__ void mma_bf16(float* c, const uint32_t* a,
                                         uint32_t b0, uint32_t b1) {
    asm volatile(
        "mma.sync.aligned.m16n8k16.row.col.f32.bf16.bf16.f32 "
        "{%0,%1,%2,%3}, {%4,%5,%6,%7}, {%8,%9}, {%0,%1,%2,%3};"
        : "+f"(c[0]), "+f"(c[1]), "+f"(c[2]), "+f"(c[3])
        : "r"(a[0]), "r"(a[1]), "r"(a[2]), "r"(a[3]), "r"(b0), "r"(b1));
}
__device__ __forceinline__ void mma_fp16(float* c, const uint32_t* a,
                                         uint32_t b0, uint32_t b1) {
    asm volatile(
        "mma.sync.aligned.m16n8k16.row.col.f32.f16.f16.f32 "
        "{%0,%1,%2,%3}, {%4,%5,%6,%7}, {%8,%9}, {%0,%1,%2,%3};"
        : "+f"(c[0]), "+f"(c[1]), "+f"(c[2]), "+f"(c[3])
        : "r"(a[0]), "r"(a[1]), "r"(a[2]), "r"(a[3]), "r"(b0), "r"(b1));
}
__device__ __forceinline__ float ex2f(float x) {
    float y;
    asm("ex2.approx.f32 %0, %1;" : "=f"(y) : "f"(x));
    return y;
}
__device__ __forceinline__ uint32_t b2u(__nv_bfloat162 v) {
    return *reinterpret_cast<uint32_t*>(&v);
}
__device__ __forceinline__ uint32_t h2u(__half2 v) {
    return *reinterpret_cast<uint32_t*>(&v);
}
__device__ __forceinline__ void cp16(uint32_t dst, const void* src) {
    asm volatile("cp.async.cg.shared.global [%0], [%1], 16;" :: "r"(dst), "l"(src));
}
#define CP_COMMIT() asm volatile("cp.async.commit_group;" ::: "memory")
#define CP_WAIT0()  asm volatile("cp.async.wait_group 0;" ::: "memory")

// ---------------------------------------------------------------------------
// Fused prep kernel
// ---------------------------------------------------------------------------
__global__ void prep_kernel(const float* __restrict__ x,
                            const float* __restrict__ pos,
                            const float* __restrict__ freqs,
                            const float* __restrict__ WQ,
                            const float* __restrict__ WK,
                            const float* __restrict__ WV,
                            const float* __restrict__ WO) {
    const int bid = blockIdx.x;
    if (bid < 2048) {
        int i = bid * 256 + threadIdx.x;
        float4 v = ((const float4*)x)[i];
        float vv[4] = {v.x, v.y, v.z, v.w};
#pragma unroll
        for (int j = 0; j < 4; j++) {
            __nv_bfloat16 h = __float2bfloat16(vv[j]);
            __nv_bfloat16 l = __float2bfloat16(vv[j] - __bfloat162float(h));
            g_xh[4 * i + j] = h;
            g_xl[4 * i + j] = l;
        }
        if (i < NH * SEQ * 32) {
            int m = i & 31;
            int n = (i >> 5) & 1023;
            int h = i >> 15;
            float ang = pos[n * 2 + 0] * freqs[(h * 32 + m) * 2 + 0]
                      + pos[n * 2 + 1] * freqs[(h * 32 + m) * 2 + 1];
            float s, c;
            sincosf(ang, &s, &c);
            g_cs[i] = make_float2(c, s);
        }
    } else {
        __shared__ float t[32][33];
        const int wb = bid - 2048;          // 0..1023
        const int z  = wb >> 8;             // 0..3
        const float* W = (z == 0) ? WQ : (z == 1) ? WK : (z == 2) ? WV : WO;
        const int zoff = z * 512;
        const int rest = wb & 255;
        const int k0 = (rest & 15) * 32, n0 = (rest >> 4) * 32;
        const int tx = threadIdx.x & 31, ty = threadIdx.x >> 5;   // 32 x 8
#pragma unroll
        for (int i = 0; i < 4; i++)
            t[ty + i * 8][tx] = W[(k0 + ty + i * 8) * 512 + n0 + tx];
        __syncthreads();
#pragma unroll
        for (int i = 0; i < 4; i++) {
            float v = t[tx][ty + i * 8];
            __nv_bfloat16 h = __float2bfloat16(v);
            __nv_bfloat16 l = __float2bfloat16(v - __bfloat162float(h));
            int dst = (zoff + n0 + ty + i * 8) * 512 + k0 + tx;
            g_Wth[dst] = h;
            g_Wtl[dst] = l;
        }
    }
}

// ---------------------------------------------------------------------------
// Split-bf16 GEMM core: block tile 128x128, BK=32, 8 warps (2m x 4n),
// warp tile 64x32. cp.async 2-stage, one barrier per chunk. (R13 config.)
// ---------------------------------------------------------------------------
#define APAD 40
#define ABY  (128*APAD*2)    // 10240 B per array
#define GBUF (4*ABY)         // 40960 B per stage
#define GEMM_SMEM (2*GBUF)   // 81920 B

struct GemmFrag { float acc[4][4][4]; };

__device__ __forceinline__ void gemm_core(
    const __nv_bfloat16* __restrict__ Ah, const __nv_bfloat16* __restrict__ Al,
    const __nv_bfloat16* __restrict__ Bh, const __nv_bfloat16* __restrict__ Bl,
    GemmFrag& fr)
{
    extern __shared__ char sm[];
    const uint32_t sb = smem_u32(sm);
    const int tid  = threadIdx.x;
    const int wid  = tid >> 5, lane = tid & 31;
    const int wm   = wid >> 2, wn = wid & 3;
    const int g    = lane >> 3, r = lane & 7;

#pragma unroll
    for (int i = 0; i < 4; i++)
#pragma unroll
        for (int j = 0; j < 4; j++)
#pragma unroll
            for (int k = 0; k < 4; k++) fr.acc[i][j][k] = 0.f;

    const int c0row = tid >> 2, c0cb = tid & 3;
    const int c1row = (tid + 256) >> 2;
    const uint32_t d0 = sb + c0row * (APAD * 2) + c0cb * 16;
    const uint32_t d1 = sb + c1row * (APAD * 2) + c0cb * 16;
    const size_t s0 = (size_t)c0row * 512 + c0cb * 8;
    const size_t s1 = (size_t)c1row * 512 + c0cb * 8;

    const uint32_t aBH = sb + (wm * 64 + (g & 1) * 8 + r) * (APAD * 2) + ((g >> 1) * 8) * 2;
    const uint32_t aBL = aBH + ABY;
    const uint32_t bBH = sb + 2 * ABY + (wn * 32 + (g >> 1) * 8 + r) * (APAD * 2) + ((g & 1) * 8) * 2;
    const uint32_t bBL = bBH + ABY;

    {
        cp16(d0 + 0 * ABY, Ah + s0); cp16(d1 + 0 * ABY, Ah + s1);
        cp16(d0 + 1 * ABY, Al + s0); cp16(d1 + 1 * ABY, Al + s1);
        cp16(d0 + 2 * ABY, Bh + s0); cp16(d1 + 2 * ABY, Bh + s1);
        cp16(d0 + 3 * ABY, Bl + s0); cp16(d1 + 3 * ABY, Bl + s1);
        CP_COMMIT();
    }

#pragma unroll 1
    for (int kc = 0; kc < 16; kc++) {
        CP_WAIT0();
        __syncthreads();
        if (kc < 15) {
            const int k1 = (kc + 1) * 32;
            const uint32_t off = ((kc + 1) & 1) * GBUF;
            cp16(d0 + off + 0 * ABY, Ah + s0 + k1); cp16(d1 + off + 0 * ABY, Ah + s1 + k1);
            cp16(d0 + off + 1 * ABY, Al + s0 + k1); cp16(d1 + off + 1 * ABY, Al + s1 + k1);
            cp16(d0 + off + 2 * ABY, Bh + s0 + k1); cp16(d1 + off + 2 * ABY, Bh + s1 + k1);
            cp16(d0 + off + 3 * ABY, Bl + s0 + k1); cp16(d1 + off + 3 * ABY, Bl + s1 + k1);
            CP_COMMIT();
        }

        const uint32_t off = (kc & 1) * GBUF;
#pragma unroll
        for (int ks = 0; ks < 2; ks++) {
            const uint32_t koff = off + ks * 32;
            uint32_t ah[4][4], al[4][4], bh[2][4], bl[2][4];
#pragma unroll
            for (int mt = 0; mt < 4; mt++) {
                ldsm_x4(aBH + mt * (16 * APAD * 2) + koff, ah[mt][0], ah[mt][1], ah[mt][2], ah[mt][3]);
                ldsm_x4(aBL + mt * (16 * APAD * 2) + koff, al[mt][0], al[mt][1], al[mt][2], al[mt][3]);
            }
#pragma unroll
            for (int nt = 0; nt < 2; nt++) {
                ldsm_x4(bBH + nt * (16 * APAD * 2) + koff, bh[nt][0], bh[nt][1], bh[nt][2], bh[nt][3]);
                ldsm_x4(bBL + nt * (16 * APAD * 2) + koff, bl[nt][0], bl[nt][1], bl[nt][2], bl[nt][3]);
            }
#pragma unroll
            for (int mt = 0; mt < 4; mt++)
#pragma unroll
                for (int ng = 0; ng < 4; ng++) {
                    const int nt = ng >> 1, p = (ng & 1) * 2;
                    mma_bf16(fr.acc[mt][ng], ah[mt], bh[nt][p], bh[nt][p + 1]);
                    mma_bf16(fr.acc[mt][ng], ah[mt], bl[nt][p], bl[nt][p + 1]);
                    mma_bf16(fr.acc[mt][ng], al[mt], bh[nt][p], bh[nt][p + 1]);
                }
        }
    }
}

// QKV projection: grid (12, 32), 256 threads. Fused RoPE + split epilogue.
// Q, K -> bf16 hi/lo (rotated); V -> single fp16.
__global__ void __launch_bounds__(256) qkv_gemm_mma() {
    const int gn0 = blockIdx.x * 128;
    const int sel = gn0 >> 9;
    const int hb  = (gn0 >> 6) & 7;
    const int m0  = blockIdx.y * 128;

    GemmFrag fr;
    gemm_core(g_xh + (size_t)m0 * 512, g_xl + (size_t)m0 * 512,
              g_Wth + (size_t)gn0 * 512, g_Wtl + (size_t)gn0 * 512, fr);

    const int wid = threadIdx.x >> 5, lane = threadIdx.x & 31;
    const int wm = wid >> 2, wn = wid & 3;

#pragma unroll
    for (int mt = 0; mt < 4; mt++) {
        int row0 = wm * 64 + mt * 16 + (lane >> 2);
#pragma unroll
        for (int ng = 0; ng < 4; ng++) {
            int col = wn * 32 + ng * 8 + (lane & 3) * 2;
            int h2 = hb + (col >> 6);
            int hd = col & 63;
            float v0 = fr.acc[mt][ng][0], v1 = fr.acc[mt][ng][1];
            float v2 = fr.acc[mt][ng][2], v3 = fr.acc[mt][ng][3];
            int tok0 = m0 + row0, tok1 = tok0 + 8;
            size_t off0 = ((size_t)((tok0 >> 10) * 8 + h2) * 1024 + (tok0 & 1023)) * 64 + hd;
            size_t off1 = ((size_t)((tok1 >> 10) * 8 + h2) * 1024 + (tok1 & 1023)) * 64 + hd;
            if (sel == 2) {
                *(uint32_t*)&g_Vfh[off0] = h2u(__floats2half2_rn(v0, v1));
                *(uint32_t*)&g_Vfh[off1] = h2u(__floats2half2_rn(v2, v3));
            } else {
                int mp = hd >> 1;
                float2 cs0 = g_cs[(h2 * 1024 + (tok0 & 1023)) * 32 + mp];
                float2 cs1 = g_cs[(h2 * 1024 + (tok1 & 1023)) * 32 + mp];
                float a0 = v0, b0 = v1;
                v0 = a0 * cs0.x - b0 * cs0.y;
                v1 = a0 * cs0.y + b0 * cs0.x;
                float a1 = v2, b1 = v3;
                v2 = a1 * cs1.x - b1 * cs1.y;
                v3 = a1 * cs1.y + b1 * cs1.x;
                __nv_bfloat16* Dh = (sel == 0) ? g_Qbh : g_Kbh;
                __nv_bfloat16* Dl = (sel == 0) ? g_Qbl : g_Kbl;
                __nv_bfloat162 hi0 = __floats2bfloat162_rn(v0, v1);
                __nv_bfloat162 hi1 = __floats2bfloat162_rn(v2, v3);
                float2 f0 = __bfloat1622float2(hi0);
                float2 f1 = __bfloat1622float2(hi1);
                __nv_bfloat162 lo0 = __floats2bfloat162_rn(v0 - f0.x, v1 - f0.y);
                __nv_bfloat162 lo1 = __floats2bfloat162_rn(v2 - f1.x, v3 - f1.y);
                *(uint32_t*)&Dh[off0] = b2u(hi0);
                *(uint32_t*)&Dl[off0] = b2u(lo0);
                *(uint32_t*)&Dh[off1] = b2u(hi1);
                *(uint32_t*)&Dl[off1] = b2u(lo1);
            }
        }
    }
}

// Output projection: grid (4, 32), 256 threads, fp32 direct to out.
__global__ void __launch_bounds__(256) out_gemm_mma(float* __restrict__ out) {
    const int n0 = blockIdx.x * 128;
    const int m0 = blockIdx.y * 128;
    GemmFrag fr;
    gemm_core(g_Ah + (size_t)m0 * 512, g_Al + (size_t)m0 * 512,
              g_Wth + (size_t)(1536 + n0) * 512, g_Wtl + (size_t)(1536 + n0) * 512, fr);

    const int wid = threadIdx.x >> 5, lane = threadIdx.x & 31;
    const int wm = wid >> 2, wn = wid & 3;
    float* C = out + (size_t)m0 * 512 + n0;
#pragma unroll
    for (int mt = 0; mt < 4; mt++) {
        int row0 = wm * 64 + mt * 16 + (lane >> 2);
#pragma unroll
        for (int ng = 0; ng < 4; ng++) {
            int col = wn * 32 + ng * 8 + (lane & 3) * 2;
            *(float2*)(C + (size_t)row0 * 512 + col) =
                make_float2(fr.acc[mt][ng][0], fr.acc[mt][ng][1]);
            *(float2*)(C + (size_t)(row0 + 8) * 512 + col) =
                make_float2(fr.acc[mt][ng][2], fr.acc[mt][ng][3]);
        }
    }
}

// ---------------------------------------------------------------------------
// Tensor-core flash attention.
//   S = 3-term split-bf16 (QhKh + QhKl + QlKh)
//   O = fp16 P x Vfh (single term — V fp16 rounding enters output at RMS)
// Fixed-reference softmax, Q persistent in smem, cp.async double-buffered
// K/V, one barrier per key block. Stage = [Kh | Kl | Vfh] (27648 B).
// ---------------------------------------------------------------------------
#define APAD2 72
#define KBY    (64*APAD2*2)     // 9216 B per array
#define KSTAGE (3*KBY)          // 27648 B per stage
#define QOFF   (2*KSTAGE)       // 55296
#define QBY    (128*APAD2*2)    // 18432 B per Q array
#define ATTN_SMEM (QOFF + 2*QBY)   // 92160 B

__global__ void __launch_bounds__(128) attn_mma_kernel()
{
    extern __shared__ char sm[];
    const uint32_t sb = smem_u32(sm);

    const int bh = blockIdx.y;
    const int b = bh >> 3, h = bh & 7;
    const int q0 = blockIdx.x * 128;
    const int tid = threadIdx.x, wid = tid >> 5, lane = tid & 31;
    const int g = lane >> 3, r = lane & 7;
    const float cs = 0.25500300f;    // (1/sqrt(32)) * log2(e)

    const size_t base = (size_t)bh * SEQ * 64;
    const __nv_bfloat16* Qh = g_Qbh + base + (size_t)q0 * 64;
    const __nv_bfloat16* Ql = g_Qbl + base + (size_t)q0 * 64;
    const __nv_bfloat16* Kh = g_Kbh + base;
    const __nv_bfloat16* Kl = g_Kbl + base;
    const __half*        Vh = g_Vfh + base;

    uint32_t e[4];
    size_t t[4];
#pragma unroll
    for (int u = 0; u < 4; u++) {
        int idx = u * 128 + tid;
        e[u] = sb + (idx >> 3) * (APAD2 * 2) + (idx & 7) * 16;
        t[u] = (size_t)(idx >> 3) * 64 + (idx & 7) * 8;
    }

    // prologue group: Q (persistent, hi+lo) + K/V block 0
#pragma unroll
    for (int u = 0; u < 8; u++) {
        int idx = u * 128 + tid;
        uint32_t dst = sb + QOFF + (idx >> 3) * (APAD2 * 2) + (idx & 7) * 16;
        size_t src = (size_t)(idx >> 3) * 64 + (idx & 7) * 8;
        cp16(dst, Qh + src);
        cp16(dst + QBY, Ql + src);
    }
#pragma unroll
    for (int u = 0; u < 4; u++) {
        cp16(e[u] + 0 * KBY, Kh + t[u]);
        cp16(e[u] + 1 * KBY, Kl + t[u]);
        cp16(e[u] + 2 * KBY, Vh + t[u]);
    }
    CP_COMMIT();

    float accO[2][8][4];
#pragma unroll
    for (int mt = 0; mt < 2; mt++)
#pragma unroll
        for (int t2 = 0; t2 < 8; t2++)
#pragma unroll
            for (int j = 0; j < 4; j++) accO[mt][t2][j] = 0.f;
    float ll[2][2];
#pragma unroll
    for (int mt = 0; mt < 2; mt++) { ll[mt][0] = 0.f; ll[mt][1] = 0.f; }

#pragma unroll 1
    for (int kb = 0; kb < 16; kb++) {
        CP_WAIT0();
        __syncthreads();
        if (kb < 15) {
            const size_t koff = (size_t)(kb + 1) * 64 * 64;
            const uint32_t off = ((kb + 1) & 1) * KSTAGE;
#pragma unroll
            for (int u = 0; u < 4; u++) {
                cp16(e[u] + off + 0 * KBY, Kh + koff + t[u]);
                cp16(e[u] + off + 1 * KBY, Kl + koff + t[u]);
                cp16(e[u] + off + 2 * KBY, Vh + koff + t[u]);
            }
            CP_COMMIT();
        }
        const uint32_t off = (kb & 1) * KSTAGE;

        // ---- S = Q K^T (split-bf16, 3 terms)
        float S[2][8][4];
#pragma unroll
        for (int mt = 0; mt < 2; mt++)
#pragma unroll
            for (int t2 = 0; t2 < 8; t2++)
#pragma unroll
                for (int j = 0; j < 4; j++) S[mt][t2][j] = 0.f;
#pragma unroll
        for (int ks = 0; ks < 4; ks++) {
            uint32_t qh[2][4], ql[2][4];
#pragma unroll
            for (int mt = 0; mt < 2; mt++) {
                uint32_t qa = sb + QOFF
                            + (wid * 32 + mt * 16 + (g & 1) * 8 + r) * (APAD2 * 2)
                            + (ks * 16 + (g >> 1) * 8) * 2;
                ldsm_x4(qa, qh[mt][0], qh[mt][1], qh[mt][2], qh[mt][3]);
                ldsm_x4(qa + QBY, ql[mt][0], ql[mt][1], ql[mt][2], ql[mt][3]);
            }
#pragma unroll
            for (int ng = 0; ng < 4; ng++) {
                uint32_t kh[4], kl[4];
                uint32_t aH = sb + off + (ng * 16 + (g >> 1) * 8 + r) * (APAD2 * 2)
                            + (ks * 16 + (g & 1) * 8) * 2;
                ldsm_x4(aH, kh[0], kh[1], kh[2], kh[3]);
                ldsm_x4(aH + KBY, kl[0], kl[1], kl[2], kl[3]);
#pragma unroll
                for (int mt = 0; mt < 2; mt++) {
                    mma_bf16(S[mt][ng * 2 + 0], qh[mt], kh[0], kh[1]);
                    mma_bf16(S[mt][ng * 2 + 1], qh[mt], kh[2], kh[3]);
                    mma_bf16(S[mt][ng * 2 + 0], qh[mt], kl[0], kl[1]);
                    mma_bf16(S[mt][ng * 2 + 1], qh[mt], kl[2], kl[3]);
                    mma_bf16(S[mt][ng * 2 + 0], ql[mt], kh[0], kh[1]);
                    mma_bf16(S[mt][ng * 2 + 1], ql[mt], kh[2], kh[3]);
                }
            }
        }

        // ---- fixed-reference softmax: p = 2^(s*cs)
#pragma unroll
        for (int mt = 0; mt < 2; mt++) {
            float s0 = 0.f, s1 = 0.f;
#pragma unroll
            for (int t2 = 0; t2 < 8; t2++) {
                S[mt][t2][0] = ex2f(S[mt][t2][0] * cs);
                S[mt][t2][1] = ex2f(S[mt][t2][1] * cs);
                S[mt][t2][2] = ex2f(S[mt][t2][2] * cs);
                S[mt][t2][3] = ex2f(S[mt][t2][3] * cs);
                s0 += S[mt][t2][0] + S[mt][t2][1];
                s1 += S[mt][t2][2] + S[mt][t2][3];
            }
            ll[mt][0] += s0;
            ll[mt][1] += s1;
        }

        // ---- O += P Vfh  (fp16, single term)
#pragma unroll
        for (int ks = 0; ks < 4; ks++) {
            uint32_t ph[2][4];
#pragma unroll
            for (int mt = 0; mt < 2; mt++) {
#pragma unroll
                for (int half = 0; half < 2; half++) {
                    int t2 = 2 * ks + half;
                    ph[mt][half * 2 + 0] = h2u(__floats2half2_rn(S[mt][t2][0], S[mt][t2][1]));
                    ph[mt][half * 2 + 1] = h2u(__floats2half2_rn(S[mt][t2][2], S[mt][t2][3]));
                }
            }
#pragma unroll
            for (int dg = 0; dg < 4; dg++) {
                uint32_t vh[4];
                uint32_t aH = sb + off + 2 * KBY + (ks * 16 + (g & 1) * 8 + r) * (APAD2 * 2)
                            + (dg * 16 + (g >> 1) * 8) * 2;
                ldsm_x4t(aH, vh[0], vh[1], vh[2], vh[3]);
#pragma unroll
                for (int mt = 0; mt < 2; mt++) {
                    mma_fp16(accO[mt][dg * 2 + 0], ph[mt], vh[0], vh[1]);
                    mma_fp16(accO[mt][dg * 2 + 1], ph[mt], vh[2], vh[3]);
                }
            }
        }
    }

    // ---- final l reduction (once)
#pragma unroll
    for (int mt = 0; mt < 2; mt++) {
        ll[mt][0] += __shfl_xor_sync(0xffffffffu, ll[mt][0], 1);
        ll[mt][0] += __shfl_xor_sync(0xffffffffu, ll[mt][0], 2);
        ll[mt][1] += __shfl_xor_sync(0xffffffffu, ll[mt][1], 1);
        ll[mt][1] += __shfl_xor_sync(0xffffffffu, ll[mt][1], 2);
    }

    // ---- epilogue: normalize + split bf16 -> g_Ah/g_Al [b][n][h][d]
#pragma unroll
    for (int mt = 0; mt < 2; mt++) {
        float inv0 = 1.f / ll[mt][0], inv1 = 1.f / ll[mt][1];
        int n_row0 = q0 + wid * 32 + mt * 16 + (lane >> 2);
#pragma unroll
        for (int t2 = 0; t2 < 8; t2++) {
            int col = t2 * 8 + (lane & 3) * 2;
            {
                float o0 = accO[mt][t2][0] * inv0, o1 = accO[mt][t2][1] * inv0;
                __nv_bfloat162 hi = __floats2bfloat162_rn(o0, o1);
                float2 f = __bfloat1622float2(hi);
                __nv_bfloat162 lo = __floats2bfloat162_rn(o0 - f.x, o1 - f.y);
                size_t off = (size_t)(b * SEQ + n_row0) * DM + h * 64 + col;
                *(uint32_t*)&g_Ah[off] = b2u(hi);
                *(uint32_t*)&g_Al[off] = b2u(lo);
            }
            {
                float o0 = accO[mt][t2][2] * inv1, o1 = accO[mt][t2][3] * inv1;
                __nv_bfloat162 hi = __floats2bfloat162_rn(o0, o1);
                float2 f = __bfloat1622float2(hi);
                __nv_bfloat162 lo = __floats2bfloat162_rn(o0 - f.x, o1 - f.y);
                size_t off = (size_t)(b * SEQ + n_row0 + 8) * DM + h * 64 + col;
                *(uint32_t*)&g_Ah[off] = b2u(hi);
                *(uint32_t*)&g_Al[off] = b2u(lo);
            }
        }
    }
}

// ---------------------------------------------------------------------------
extern "C" void kernel_launch(void* const* d_in, const int* in_sizes, int n_in,
                              void* d_out, int out_size)
{
    const float* x     = (const float*)d_in[0];
    const float* pos   = (const float*)d_in[1];
    const float* WQ    = (const float*)d_in[2];
    const float* WK    = (const float*)d_in[3];
    const float* WV    = (const float*)d_in[4];
    const float* WO    = (const float*)d_in[5];
    // d_in[6] = U: unused — qr(U).Q is a complete orthogonal basis, so P = I.
    const float* freqs = (const float*)d_in[7];
    float* out = (float*)d_out;

    cudaFuncSetAttribute(qkv_gemm_mma, cudaFuncAttributeMaxDynamicSharedMemorySize, GEMM_SMEM);
    cudaFuncSetAttribute(out_gemm_mma, cudaFuncAttributeMaxDynamicSharedMemorySize, GEMM_SMEM);
    cudaFuncSetAttribute(attn_mma_kernel, cudaFuncAttributeMaxDynamicSharedMemorySize, ATTN_SMEM);

    // 0. fused prep: x split + cs table + weight transpose/split
    prep_kernel<<<3072, 256>>>(x, pos, freqs, WQ, WK, WV, WO);
    // 1. fused QKV projection + RoPE + split (V -> single fp16)
    qkv_gemm_mma<<<dim3(12, 32), 256, GEMM_SMEM>>>();
    // 2. flash attention (bf16 S 3-term, fp16 PV single-term)
    attn_mma_kernel<<<dim3(SEQ / 128, BATCH * NH), 128, ATTN_SMEM>>>();
    // 3. output projection (2-stage, R13 config)
    out_gemm_mma<<<dim3(4, 32), 256, GEMM_SMEM>>>(out);
}

// round 17
// speedup vs baseline: 1.2534x; 1.1437x over previous
#include <cuda_runtime.h>
#include <cuda_bf16.h>
#include <cuda_fp16.h>
#include <math.h>
#include <stdint.h>

// Problem constants
#define BATCH 4
#define SEQ   1024
#define DM    512
#define NH    8
#define DH    64
#define ROWS  (BATCH*SEQ)          // 4096

// ---------------------------------------------------------------------------
// Scratch (__device__ globals: allocation-free rule)
// ---------------------------------------------------------------------------
__device__ __nv_bfloat16 g_xh[ROWS*DM];     // x split hi
__device__ __nv_bfloat16 g_xl[ROWS*DM];     // x split lo
__device__ __nv_bfloat16 g_Ah[ROWS*DM];     // attention out split hi [b][n][h][d]
__device__ __nv_bfloat16 g_Al[ROWS*DM];     // attention out split lo
// Transposed weights (n-major rows), bf16 split:
// rows 0..1535 = WQ|WK|WV, rows 1536..2047 = WO
__device__ __nv_bfloat16 g_Wth[2048*512];
__device__ __nv_bfloat16 g_Wtl[2048*512];
// Attention-layout fp16 (single precision each): [b][h][n][d]
#define BHND (32*1024*64)
__device__ __half g_Qf[BHND];
__device__ __half g_Kf[BHND];
__device__ __half g_Vf[BHND];
// RoPE cos/sin table: [h][n][m] -> float2 (cos, sin)
__device__ float2 g_cs[NH*SEQ*32];

// ---------------------------------------------------------------------------
// Helpers
// ---------------------------------------------------------------------------
__device__ __forceinline__ uint32_t smem_u32(const void* p) {
    uint32_t a;
    asm("{ .reg .u64 t; cvta.to.shared.u64 t, %1; cvt.u32.u64 %0, t; }" : "=r"(a) : "l"(p));
    return a;
}
__device__ __forceinline__ void ldsm_x4(uint32_t addr, uint32_t& r0, uint32_t& r1,
                                        uint32_t& r2, uint32_t& r3) {
    asm volatile("ldmatrix.sync.aligned.m8n8.x4.shared.b16 {%0,%1,%2,%3}, [%4];"
                 : "=r"(r0), "=r"(r1), "=r"(r2), "=r"(r3) : "r"(addr));
}
__device__ __forceinline__ void ldsm_x4t(uint32_t addr, uint32_t& r0, uint32_t& r1,
                                         uint32_t& r2, uint32_t& r3) {
    asm volatile("ldmatrix.sync.aligned.m8n8.x4.trans.shared.b16 {%0,%1,%2,%3}, [%4];"
                 : "=r"(r0), "=r"(r1), "=r"(r2), "=r"(r3) : "r"(addr));
}
__device__ __forceinline__ void mma_bf16(float* c, const uint32_t* a,
                                         uint32_t b0, uint32_t b1) {
    asm volatile(
        "mma.sync.aligned.m16n8k16.row.col.f32.bf16.bf16.f32 "
        "{%0,%1,%2,%3}, {%4,%5,%6,%7}, {%8,%9}, {%0,%1,%2,%3};"
        : "+f"(c[0]), "+f"(c[1]), "+f"(c[2]), "+f"(c[3])
        : "r"(a[0]), "r"(a[1]), "r"(a[2]), "r"(a[3]), "r"(b0), "r"(b1));
}
__device__ __forceinline__ void mma_fp16(float* c, const uint32_t* a,
                                         uint32_t b0, uint32_t b1) {
    asm volatile(
        "mma.sync.aligned.m16n8k16.row.col.f32.f16.f16.f32 "
        "{%0,%1,%2,%3}, {%4,%5,%6,%7}, {%8,%9}, {%0,%1,%2,%3};"
        : "+f"(c[0]), "+f"(c[1]), "+f"(c[2]), "+f"(c[3])
        : "r"(a[0]), "r"(a[1]), "r"(a[2]), "r"(a[3]), "r"(b0), "r"(b1));
}
__device__ __forceinline__ float ex2f(float x) {
    float y;
    asm("ex2.approx.f32 %0, %1;" : "=f"(y) : "f"(x));
    return y;
}
__device__ __forceinline__ uint32_t b2u(__nv_bfloat162 v) {
    return *reinterpret_cast<uint32_t*>(&v);
}
__device__ __forceinline__ uint32_t h2u(__half2 v) {
    return *reinterpret_cast<uint32_t*>(&v);
}
__device__ __forceinline__ void cp16(uint32_t dst, const void* src) {
    asm volatile("cp.async.cg.shared.global [%0], [%1], 16;" :: "r"(dst), "l"(src));
}
#define CP_COMMIT() asm volatile("cp.async.commit_group;" ::: "memory")
#define CP_WAIT0()  asm volatile("cp.async.wait_group 0;" ::: "memory")

// ---------------------------------------------------------------------------
// Fused prep kernel
// ---------------------------------------------------------------------------
__global__ void prep_kernel(const float* __restrict__ x,
                            const float* __restrict__ pos,
                            const float* __restrict__ freqs,
                            const float* __restrict__ WQ,
                            const float* __restrict__ WK,
                            const float* __restrict__ WV,
                            const float* __restrict__ WO) {
    const int bid = blockIdx.x;
    if (bid < 2048) {
        int i = bid * 256 + threadIdx.x;
        float4 v = ((const float4*)x)[i];
        float vv[4] = {v.x, v.y, v.z, v.w};
#pragma unroll
        for (int j = 0; j < 4; j++) {
            __nv_bfloat16 h = __float2bfloat16(vv[j]);
            __nv_bfloat16 l = __float2bfloat16(vv[j] - __bfloat162float(h));
            g_xh[4 * i + j] = h;
            g_xl[4 * i + j] = l;
        }
        if (i < NH * SEQ * 32) {
            int m = i & 31;
            int n = (i >> 5) & 1023;
            int h = i >> 15;
            float ang = pos[n * 2 + 0] * freqs[(h * 32 + m) * 2 + 0]
                      + pos[n * 2 + 1] * freqs[(h * 32 + m) * 2 + 1];
            float s, c;
            sincosf(ang, &s, &c);
            g_cs[i] = make_float2(c, s);
        }
    } else {
        __shared__ float t[32][33];
        const int wb = bid - 2048;          // 0..1023
        const int z  = wb >> 8;             // 0..3
        const float* W = (z == 0) ? WQ : (z == 1) ? WK : (z == 2) ? WV : WO;
        const int zoff = z * 512;
        const int rest = wb & 255;
        const int k0 = (rest & 15) * 32, n0 = (rest >> 4) * 32;
        const int tx = threadIdx.x & 31, ty = threadIdx.x >> 5;   // 32 x 8
#pragma unroll
        for (int i = 0; i < 4; i++)
            t[ty + i * 8][tx] = W[(k0 + ty + i * 8) * 512 + n0 + tx];
        __syncthreads();
#pragma unroll
        for (int i = 0; i < 4; i++) {
            float v = t[tx][ty + i * 8];
            __nv_bfloat16 h = __float2bfloat16(v);
            __nv_bfloat16 l = __float2bfloat16(v - __bfloat162float(h));
            int dst = (zoff + n0 + ty + i * 8) * 512 + k0 + tx;
            g_Wth[dst] = h;
            g_Wtl[dst] = l;
        }
    }
}

// ---------------------------------------------------------------------------
// Split-bf16 GEMM core: block tile 128x128, BK=32, 8 warps (2m x 4n),
// warp tile 64x32. cp.async 2-stage, one barrier per chunk. (R13 config.)
// ---------------------------------------------------------------------------
#define APAD 40
#define ABY  (128*APAD*2)    // 10240 B per array
#define GBUF (4*ABY)         // 40960 B per stage
#define GEMM_SMEM (2*GBUF)   // 81920 B

struct GemmFrag { float acc[4][4][4]; };

__device__ __forceinline__ void gemm_core(
    const __nv_bfloat16* __restrict__ Ah, const __nv_bfloat16* __restrict__ Al,
    const __nv_bfloat16* __restrict__ Bh, const __nv_bfloat16* __restrict__ Bl,
    GemmFrag& fr)
{
    extern __shared__ char sm[];
    const uint32_t sb = smem_u32(sm);
    const int tid  = threadIdx.x;
    const int wid  = tid >> 5, lane = tid & 31;
    const int wm   = wid >> 2, wn = wid & 3;
    const int g    = lane >> 3, r = lane & 7;

#pragma unroll
    for (int i = 0; i < 4; i++)
#pragma unroll
        for (int j = 0; j < 4; j++)
#pragma unroll
            for (int k = 0; k < 4; k++) fr.acc[i][j][k] = 0.f;

    const int c0row = tid >> 2, c0cb = tid & 3;
    const int c1row = (tid + 256) >> 2;
    const uint32_t d0 = sb + c0row * (APAD * 2) + c0cb * 16;
    const uint32_t d1 = sb + c1row * (APAD * 2) + c0cb * 16;
    const size_t s0 = (size_t)c0row * 512 + c0cb * 8;
    const size_t s1 = (size_t)c1row * 512 + c0cb * 8;

    const uint32_t aBH = sb + (wm * 64 + (g & 1) * 8 + r) * (APAD * 2) + ((g >> 1) * 8) * 2;
    const uint32_t aBL = aBH + ABY;
    const uint32_t bBH = sb + 2 * ABY + (wn * 32 + (g >> 1) * 8 + r) * (APAD * 2) + ((g & 1) * 8) * 2;
    const uint32_t bBL = bBH + ABY;

    {
        cp16(d0 + 0 * ABY, Ah + s0); cp16(d1 + 0 * ABY, Ah + s1);
        cp16(d0 + 1 * ABY, Al + s0); cp16(d1 + 1 * ABY, Al + s1);
        cp16(d0 + 2 * ABY, Bh + s0); cp16(d1 + 2 * ABY, Bh + s1);
        cp16(d0 + 3 * ABY, Bl + s0); cp16(d1 + 3 * ABY, Bl + s1);
        CP_COMMIT();
    }

#pragma unroll 1
    for (int kc = 0; kc < 16; kc++) {
        CP_WAIT0();
        __syncthreads();
        if (kc < 15) {
            const int k1 = (kc + 1) * 32;
            const uint32_t off = ((kc + 1) & 1) * GBUF;
            cp16(d0 + off + 0 * ABY, Ah + s0 + k1); cp16(d1 + off + 0 * ABY, Ah + s1 + k1);
            cp16(d0 + off + 1 * ABY, Al + s0 + k1); cp16(d1 + off + 1 * ABY, Al + s1 + k1);
            cp16(d0 + off + 2 * ABY, Bh + s0 + k1); cp16(d1 + off + 2 * ABY, Bh + s1 + k1);
            cp16(d0 + off + 3 * ABY, Bl + s0 + k1); cp16(d1 + off + 3 * ABY, Bl + s1 + k1);
            CP_COMMIT();
        }

        const uint32_t off = (kc & 1) * GBUF;
#pragma unroll
        for (int ks = 0; ks < 2; ks++) {
            const uint32_t koff = off + ks * 32;
            uint32_t ah[4][4], al[4][4], bh[2][4], bl[2][4];
#pragma unroll
            for (int mt = 0; mt < 4; mt++) {
                ldsm_x4(aBH + mt * (16 * APAD * 2) + koff, ah[mt][0], ah[mt][1], ah[mt][2], ah[mt][3]);
                ldsm_x4(aBL + mt * (16 * APAD * 2) + koff, al[mt][0], al[mt][1], al[mt][2], al[mt][3]);
            }
#pragma unroll
            for (int nt = 0; nt < 2; nt++) {
                ldsm_x4(bBH + nt * (16 * APAD * 2) + koff, bh[nt][0], bh[nt][1], bh[nt][2], bh[nt][3]);
                ldsm_x4(bBL + nt * (16 * APAD * 2) + koff, bl[nt][0], bl[nt][1], bl[nt][2], bl[nt][3]);
            }
#pragma unroll
            for (int mt = 0; mt < 4; mt++)
#pragma unroll
                for (int ng = 0; ng < 4; ng++) {
                    const int nt = ng >> 1, p = (ng & 1) * 2;
                    mma_bf16(fr.acc[mt][ng], ah[mt], bh[nt][p], bh[nt][p + 1]);
                    mma_bf16(fr.acc[mt][ng], ah[mt], bl[nt][p], bl[nt][p + 1]);
                    mma_bf16(fr.acc[mt][ng], al[mt], bh[nt][p], bh[nt][p + 1]);
                }
        }
    }
}

// QKV projection: grid (12, 32), 256 threads. Fused RoPE + fp16 epilogue.
// Q, K rotated then stored single fp16; V single fp16.
__global__ void __launch_bounds__(256) qkv_gemm_mma() {
    const int gn0 = blockIdx.x * 128;
    const int sel = gn0 >> 9;
    const int hb  = (gn0 >> 6) & 7;
    const int m0  = blockIdx.y * 128;

    GemmFrag fr;
    gemm_core(g_xh + (size_t)m0 * 512, g_xl + (size_t)m0 * 512,
              g_Wth + (size_t)gn0 * 512, g_Wtl + (size_t)gn0 * 512, fr);

    const int wid = threadIdx.x >> 5, lane = threadIdx.x & 31;
    const int wm = wid >> 2, wn = wid & 3;
    __half* D = (sel == 0) ? g_Qf : (sel == 1) ? g_Kf : g_Vf;

#pragma unroll
    for (int mt = 0; mt < 4; mt++) {
        int row0 = wm * 64 + mt * 16 + (lane >> 2);
#pragma unroll
        for (int ng = 0; ng < 4; ng++) {
            int col = wn * 32 + ng * 8 + (lane & 3) * 2;
            int h2 = hb + (col >> 6);
            int hd = col & 63;
            float v0 = fr.acc[mt][ng][0], v1 = fr.acc[mt][ng][1];
            float v2 = fr.acc[mt][ng][2], v3 = fr.acc[mt][ng][3];
            int tok0 = m0 + row0, tok1 = tok0 + 8;
            if (sel < 2) {
                int mp = hd >> 1;
                float2 cs0 = g_cs[(h2 * 1024 + (tok0 & 1023)) * 32 + mp];
                float2 cs1 = g_cs[(h2 * 1024 + (tok1 & 1023)) * 32 + mp];
                float a0 = v0, b0 = v1;
                v0 = a0 * cs0.x - b0 * cs0.y;
                v1 = a0 * cs0.y + b0 * cs0.x;
                float a1 = v2, b1 = v3;
                v2 = a1 * cs1.x - b1 * cs1.y;
                v3 = a1 * cs1.y + b1 * cs1.x;
            }
            size_t off0 = ((size_t)((tok0 >> 10) * 8 + h2) * 1024 + (tok0 & 1023)) * 64 + hd;
            size_t off1 = ((size_t)((tok1 >> 10) * 8 + h2) * 1024 + (tok1 & 1023)) * 64 + hd;
            *(uint32_t*)&D[off0] = h2u(__floats2half2_rn(v0, v1));
            *(uint32_t*)&D[off1] = h2u(__floats2half2_rn(v2, v3));
        }
    }
}

// Output projection: grid (4, 32), 256 threads, fp32 direct to out.
__global__ void __launch_bounds__(256) out_gemm_mma(float* __restrict__ out) {
    const int n0 = blockIdx.x * 128;
    const int m0 = blockIdx.y * 128;
    GemmFrag fr;
    gemm_core(g_Ah + (size_t)m0 * 512, g_Al + (size_t)m0 * 512,
              g_Wth + (size_t)(1536 + n0) * 512, g_Wtl + (size_t)(1536 + n0) * 512, fr);

    const int wid = threadIdx.x >> 5, lane = threadIdx.x & 31;
    const int wm = wid >> 2, wn = wid & 3;
    float* C = out + (size_t)m0 * 512 + n0;
#pragma unroll
    for (int mt = 0; mt < 4; mt++) {
        int row0 = wm * 64 + mt * 16 + (lane >> 2);
#pragma unroll
        for (int ng = 0; ng < 4; ng++) {
            int col = wn * 32 + ng * 8 + (lane & 3) * 2;
            *(float2*)(C + (size_t)row0 * 512 + col) =
                make_float2(fr.acc[mt][ng][0], fr.acc[mt][ng][1]);
            *(float2*)(C + (size_t)(row0 + 8) * 512 + col) =
                make_float2(fr.acc[mt][ng][2], fr.acc[mt][ng][3]);
        }
    }
}

// ---------------------------------------------------------------------------
// Tensor-core flash attention — full fp16 path:
//   S = Qf Kf^T (single fp16 MMA term)
//   O = P Vf    (single fp16 MMA term)
// Fixed-reference softmax, Q persistent in smem, cp.async double-buffered
// K/V, one barrier per key block. Stage = [Kf | Vf] (18432 B).
// ---------------------------------------------------------------------------
#define APAD2 72
#define KBY    (64*APAD2*2)     // 9216 B per array
#define KSTAGE (2*KBY)          // 18432 B per stage
#define QOFF   (2*KSTAGE)       // 36864
#define QBY    (128*APAD2*2)    // 18432 B (single Q array)
#define ATTN_SMEM (QOFF + QBY)  // 55296 B

__global__ void __launch_bounds__(128) attn_mma_kernel()
{
    extern __shared__ char sm[];
    const uint32_t sb = smem_u32(sm);

    const int bh = blockIdx.y;
    const int b = bh >> 3, h = bh & 7;
    const int q0 = blockIdx.x * 128;
    const int tid = threadIdx.x, wid = tid >> 5, lane = tid & 31;
    const int g = lane >> 3, r = lane & 7;
    const float cs = 0.25500300f;    // (1/sqrt(32)) * log2(e)

    const size_t base = (size_t)bh * SEQ * 64;
    const __half* Qf = g_Qf + base + (size_t)q0 * 64;
    const __half* Kf = g_Kf + base;
    const __half* Vf = g_Vf + base;

    uint32_t e[4];
    size_t t[4];
#pragma unroll
    for (int u = 0; u < 4; u++) {
        int idx = u * 128 + tid;
        e[u] = sb + (idx >> 3) * (APAD2 * 2) + (idx & 7) * 16;
        t[u] = (size_t)(idx >> 3) * 64 + (idx & 7) * 8;
    }

    // prologue group: Q (persistent) + K/V block 0
#pragma unroll
    for (int u = 0; u < 8; u++) {
        int idx = u * 128 + tid;
        uint32_t dst = sb + QOFF + (idx >> 3) * (APAD2 * 2) + (idx & 7) * 16;
        size_t src = (size_t)(idx >> 3) * 64 + (idx & 7) * 8;
        cp16(dst, Qf + src);
    }
#pragma unroll
    for (int u = 0; u < 4; u++) {
        cp16(e[u] + 0 * KBY, Kf + t[u]);
        cp16(e[u] + 1 * KBY, Vf + t[u]);
    }
    CP_COMMIT();

    float accO[2][8][4];
#pragma unroll
    for (int mt = 0; mt < 2; mt++)
#pragma unroll
        for (int t2 = 0; t2 < 8; t2++)
#pragma unroll
            for (int j = 0; j < 4; j++) accO[mt][t2][j] = 0.f;
    float ll[2][2];
#pragma unroll
    for (int mt = 0; mt < 2; mt++) { ll[mt][0] = 0.f; ll[mt][1] = 0.f; }

#pragma unroll 1
    for (int kb = 0; kb < 16; kb++) {
        CP_WAIT0();
        __syncthreads();
        if (kb < 15) {
            const size_t koff = (size_t)(kb + 1) * 64 * 64;
            const uint32_t off = ((kb + 1) & 1) * KSTAGE;
#pragma unroll
            for (int u = 0; u < 4; u++) {
                cp16(e[u] + off + 0 * KBY, Kf + koff + t[u]);
                cp16(e[u] + off + 1 * KBY, Vf + koff + t[u]);
            }
            CP_COMMIT();
        }
        const uint32_t off = (kb & 1) * KSTAGE;

        // ---- S = Qf Kf^T (single fp16 term)
        float S[2][8][4];
#pragma unroll
        for (int mt = 0; mt < 2; mt++)
#pragma unroll
            for (int t2 = 0; t2 < 8; t2++)
#pragma unroll
                for (int j = 0; j < 4; j++) S[mt][t2][j] = 0.f;
#pragma unroll
        for (int ks = 0; ks < 4; ks++) {
            uint32_t qf[2][4];
#pragma unroll
            for (int mt = 0; mt < 2; mt++) {
                uint32_t qa = sb + QOFF
                            + (wid * 32 + mt * 16 + (g & 1) * 8 + r) * (APAD2 * 2)
                            + (ks * 16 + (g >> 1) * 8) * 2;
                ldsm_x4(qa, qf[mt][0], qf[mt][1], qf[mt][2], qf[mt][3]);
            }
#pragma unroll
            for (int ng = 0; ng < 4; ng++) {
                uint32_t kf[4];
                uint32_t aH = sb + off + (ng * 16 + (g >> 1) * 8 + r) * (APAD2 * 2)
                            + (ks * 16 + (g & 1) * 8) * 2;
                ldsm_x4(aH, kf[0], kf[1], kf[2], kf[3]);
#pragma unroll
                for (int mt = 0; mt < 2; mt++) {
                    mma_fp16(S[mt][ng * 2 + 0], qf[mt], kf[0], kf[1]);
                    mma_fp16(S[mt][ng * 2 + 1], qf[mt], kf[2], kf[3]);
                }
            }
        }

        // ---- fixed-reference softmax: p = 2^(s*cs)
#pragma unroll
        for (int mt = 0; mt < 2; mt++) {
            float s0 = 0.f, s1 = 0.f;
#pragma unroll
            for (int t2 = 0; t2 < 8; t2++) {
                S[mt][t2][0] = ex2f(S[mt][t2][0] * cs);
                S[mt][t2][1] = ex2f(S[mt][t2][1] * cs);
                S[mt][t2][2] = ex2f(S[mt][t2][2] * cs);
                S[mt][t2][3] = ex2f(S[mt][t2][3] * cs);
                s0 += S[mt][t2][0] + S[mt][t2][1];
                s1 += S[mt][t2][2] + S[mt][t2][3];
            }
            ll[mt][0] += s0;
            ll[mt][1] += s1;
        }

        // ---- O += P Vf  (single fp16 term)
#pragma unroll
        for (int ks = 0; ks < 4; ks++) {
            uint32_t ph[2][4];
#pragma unroll
            for (int mt = 0; mt < 2; mt++) {
#pragma unroll
                for (int half = 0; half < 2; half++) {
                    int t2 = 2 * ks + half;
                    ph[mt][half * 2 + 0] = h2u(__floats2half2_rn(S[mt][t2][0], S[mt][t2][1]));
                    ph[mt][half * 2 + 1] = h2u(__floats2half2_rn(S[mt][t2][2], S[mt][t2][3]));
                }
            }
#pragma unroll
            for (int dg = 0; dg < 4; dg++) {
                uint32_t vh[4];
                uint32_t aH = sb + off + 1 * KBY + (ks * 16 + (g & 1) * 8 + r) * (APAD2 * 2)
                            + (dg * 16 + (g >> 1) * 8) * 2;
                ldsm_x4t(aH, vh[0], vh[1], vh[2], vh[3]);
#pragma unroll
                for (int mt = 0; mt < 2; mt++) {
                    mma_fp16(accO[mt][dg * 2 + 0], ph[mt], vh[0], vh[1]);
                    mma_fp16(accO[mt][dg * 2 + 1], ph[mt], vh[2], vh[3]);
                }
            }
        }
    }

    // ---- final l reduction (once)
#pragma unroll
    for (int mt = 0; mt < 2; mt++) {
        ll[mt][0] += __shfl_xor_sync(0xffffffffu, ll[mt][0], 1);
        ll[mt][0] += __shfl_xor_sync(0xffffffffu, ll[mt][0], 2);
        ll[mt][1] += __shfl_xor_sync(0xffffffffu, ll[mt][1], 1);
        ll[mt][1] += __shfl_xor_sync(0xffffffffu, ll[mt][1], 2);
    }

    // ---- epilogue: normalize + split bf16 -> g_Ah/g_Al [b][n][h][d]
#pragma unroll
    for (int mt = 0; mt < 2; mt++) {
        float inv0 = 1.f / ll[mt][0], inv1 = 1.f / ll[mt][1];
        int n_row0 = q0 + wid * 32 + mt * 16 + (lane >> 2);
#pragma unroll
        for (int t2 = 0; t2 < 8; t2++) {
            int col = t2 * 8 + (lane & 3) * 2;
            {
                float o0 = accO[mt][t2][0] * inv0, o1 = accO[mt][t2][1] * inv0;
                __nv_bfloat162 hi = __floats2bfloat162_rn(o0, o1);
                float2 f = __bfloat1622float2(hi);
                __nv_bfloat162 lo = __floats2bfloat162_rn(o0 - f.x, o1 - f.y);
                size_t off = (size_t)(b * SEQ + n_row0) * DM + h * 64 + col;
                *(uint32_t*)&g_Ah[off] = b2u(hi);
                *(uint32_t*)&g_Al[off] = b2u(lo);
            }
            {
                float o0 = accO[mt][t2][2] * inv1, o1 = accO[mt][t2][3] * inv1;
                __nv_bfloat162 hi = __floats2bfloat162_rn(o0, o1);
                float2 f = __bfloat1622float2(hi);
                __nv_bfloat162 lo = __floats2bfloat162_rn(o0 - f.x, o1 - f.y);
                size_t off = (size_t)(b * SEQ + n_row0 + 8) * DM + h * 64 + col;
                *(uint32_t*)&g_Ah[off] = b2u(hi);
                *(uint32_t*)&g_Al[off] = b2u(lo);
            }
        }
    }
}

// ---------------------------------------------------------------------------
extern "C" void kernel_launch(void* const* d_in, const int* in_sizes, int n_in,
                              void* d_out, int out_size)
{
    const float* x     = (const float*)d_in[0];
    const float* pos   = (const float*)d_in[1];
    const float* WQ    = (const float*)d_in[2];
    const float* WK    = (const float*)d_in[3];
    const float* WV    = (const float*)d_in[4];
    const float* WO    = (const float*)d_in[5];
    // d_in[6] = U: unused — qr(U).Q is a complete orthogonal basis, so P = I.
    const float* freqs = (const float*)d_in[7];
    float* out = (float*)d_out;

    cudaFuncSetAttribute(qkv_gemm_mma, cudaFuncAttributeMaxDynamicSharedMemorySize, GEMM_SMEM);
    cudaFuncSetAttribute(out_gemm_mma, cudaFuncAttributeMaxDynamicSharedMemorySize, GEMM_SMEM);
    cudaFuncSetAttribute(attn_mma_kernel, cudaFuncAttributeMaxDynamicSharedMemorySize, ATTN_SMEM);

    // 0. fused prep: x split + cs table + weight transpose/split
    prep_kernel<<<3072, 256>>>(x, pos, freqs, WQ, WK, WV, WO);
    // 1. fused QKV projection + RoPE (Q/K/V -> single fp16)
    qkv_gemm_mma<<<dim3(12, 32), 256, GEMM_SMEM>>>();
    // 2. flash attention (full fp16: single-term S and PV)
    attn_mma_kernel<<<dim3(SEQ / 128, BATCH * NH), 128, ATTN_SMEM>>>();
    // 3. output projection (2-stage split-bf16)
    out_gemm_mma<<<dim3(4, 32), 256, GEMM_SMEM>>>(out);
}